// round 12
// baseline (speedup 1.0000x reference)
#include <cuda_runtime.h>
#include <cuda_bf16.h>
#include <math.h>
#include <stdint.h>

#define HID 1024
#define NH 4
#define DK 256
#define DV 256
#define CHUNK 32
#define TMAX 8192
#define QP 260
#define KTP 36
#define NC 16

// ---------------- scratch ----------------
__device__ float g_tmp3 [TMAX*3*HID];
__device__ float g_q    [TMAX*HID];
__device__ float g_k    [TMAX*HID];
__device__ float g_v    [TMAX*HID];
__device__ float g_kb   [TMAX*HID];
__device__ float g_u    [TMAX*HID];
__device__ float g_w    [TMAX*HID];
__device__ float g_del  [TMAX*HID];
__device__ float g_ls   [TMAX*HID];
__device__ float g_ll   [TMAX*HID];
__device__ float g_g1   [TMAX*HID];
__device__ float g_aloc [TMAX*NH*CHUNK];
__device__ float g_beta [TMAX*NH];
__device__ __nv_bfloat16 g_a2 [TMAX*2*HID];
__device__ __nv_bfloat16 g_bth[3*HID*HID];
__device__ __nv_bfloat16 g_btl[3*HID*HID];
__device__ __nv_bfloat16 g_bthg[HID*HID];
__device__ __nv_bfloat16 g_btlg[HID*HID];
__device__ __nv_bfloat16 g_btho[HID*HID];
__device__ __nv_bfloat16 g_btlo[HID*HID];

__device__ __forceinline__ uint32_t smem_u32(const void* p) {
    uint32_t a;
    asm("{ .reg .u64 t; cvta.to.shared.u64 t, %1; cvt.u32.u64 %0, t; }" : "=r"(a) : "l"(p));
    return a;
}
__device__ __forceinline__ void cp16(uint32_t dst, const void* src) {
    asm volatile("cp.async.cg.shared.global [%0], [%1], 16;" :: "r"(dst), "l"(src));
}

// ---------------- precision-split prep ----------------
__global__ void asplit_kernel(const float* __restrict__ X,
                              __nv_bfloat16* __restrict__ A2, int K, int total) {
    int idx = blockIdx.x * blockDim.x + threadIdx.x;
    if (idx >= total) return;
    int m = idx / K, kk = idx - m * K;
    float v = X[idx];
    __nv_bfloat16 hi = __float2bfloat16(v);
    float r = v - __bfloat162float(hi);
    A2[(size_t)m * 2 * K + kk]     = hi;
    A2[(size_t)m * 2 * K + K + kk] = __float2bfloat16(r);
}

__global__ void bsplit_kernel(const float* __restrict__ W,
                              __nv_bfloat16* __restrict__ Bh,
                              __nv_bfloat16* __restrict__ Bl, int K, int N) {
    __shared__ float t[32][33];
    int bn = blockIdx.x * 32, bk = blockIdx.y * 32;
    int x = threadIdx.x, y = threadIdx.y;
    for (int i = y; i < 32; i += 8) t[i][x] = W[(size_t)(bk + i) * N + bn + x];
    __syncthreads();
    for (int i = y; i < 32; i += 8) {
        float v = t[x][i];
        __nv_bfloat16 hi = __float2bfloat16(v);
        float r = v - __bfloat162float(hi);
        Bh[(size_t)(bn + i) * K + bk + x] = hi;
        Bl[(size_t)(bn + i) * K + bk + x] = __float2bfloat16(r);
    }
}

// ---------------- bf16 mma.sync GEMM (3-term split), BK=64, 3-stage -------------
#define BM 128
#define BN 128
#define BK 64
#define APITCH 72
#define ASTAGE (BM * APITCH * 2)
#define GSTAGE (2 * ASTAGE)
#define SST 3

__global__ __launch_bounds__(256) void gemm_mma(
    const __nv_bfloat16* __restrict__ A2, const __nv_bfloat16* __restrict__ Bh,
    const __nv_bfloat16* __restrict__ Bl, float* __restrict__ C,
    int M, int N, int K)
{
    extern __shared__ __align__(16) char gsm[];
    uint32_t sb = smem_u32(gsm);

    const int tid = threadIdx.x;
    const int wid = tid >> 5, lane = tid & 31;
    const int m0 = blockIdx.y * BM, n0 = blockIdx.x * BN;
    const int wm = (wid >> 2) * 64, wn = (wid & 3) * 32;

    const int KBn = K / BK;
    const int NB = 3 * KBn;
    const size_t sA = (size_t)2 * K;

    auto load_stage = [&](int kb, int buf) {
        int seg = kb / KBn;
        int kk = (kb - seg * KBn) * BK;
        const __nv_bfloat16* Ap = A2 + (seg == 1 ? (size_t)K : 0) + kk;
        const __nv_bfloat16* Bp = ((seg == 2) ? Bl : Bh) + kk;
        uint32_t a_s = sb + (uint32_t)buf * GSTAGE;
        uint32_t b_s = a_s + ASTAGE;
#pragma unroll
        for (int i = 0; i < 4; ++i) {
            int idx = i * 256 + tid;
            int row = idx >> 3, ch = idx & 7;
            cp16(a_s + (uint32_t)(row * APITCH + ch * 8) * 2,
                 Ap + (size_t)(m0 + row) * sA + ch * 8);
            cp16(b_s + (uint32_t)(row * APITCH + ch * 8) * 2,
                 Bp + (size_t)(n0 + row) * K + ch * 8);
        }
    };

    float acc[4][4][4];
#pragma unroll
    for (int mt = 0; mt < 4; ++mt)
#pragma unroll
        for (int nt = 0; nt < 4; ++nt)
#pragma unroll
            for (int e = 0; e < 4; ++e) acc[mt][nt][e] = 0.f;

    load_stage(0, 0);
    asm volatile("cp.async.commit_group;" ::: "memory");
    load_stage(1, 1);
    asm volatile("cp.async.commit_group;" ::: "memory");

    int buf = 0;
    for (int kb = 0; kb < NB; ++kb) {
        asm volatile("cp.async.wait_group 1;" ::: "memory");
        __syncthreads();
        if (kb + 2 < NB) load_stage(kb + 2, (buf + 2) % SST);
        asm volatile("cp.async.commit_group;" ::: "memory");

        uint32_t a_s = sb + (uint32_t)buf * GSTAGE;
        uint32_t b_s = a_s + ASTAGE;
#pragma unroll
        for (int kp = 0; kp < 4; ++kp) {
            uint32_t a[4][4], b[4][2];
            {
                int r_off = lane & 15;
                int c_off = kp * 16 + (lane >> 4) * 8;
#pragma unroll
                for (int mt = 0; mt < 4; ++mt) {
                    uint32_t addr = a_s + (uint32_t)((wm + mt * 16 + r_off) * APITCH + c_off) * 2;
                    asm volatile("ldmatrix.sync.aligned.m8n8.x4.shared.b16 {%0,%1,%2,%3}, [%4];"
                        : "=r"(a[mt][0]), "=r"(a[mt][1]), "=r"(a[mt][2]), "=r"(a[mt][3])
                        : "r"(addr));
                }
            }
            {
                int n_off = (lane & 7) + (lane >> 4) * 8;
                int c_off = kp * 16 + ((lane >> 3) & 1) * 8;
#pragma unroll
                for (int nb = 0; nb < 2; ++nb) {
                    uint32_t r0, r1, r2, r3;
                    uint32_t addr = b_s + (uint32_t)((wn + nb * 16 + n_off) * APITCH + c_off) * 2;
                    asm volatile("ldmatrix.sync.aligned.m8n8.x4.shared.b16 {%0,%1,%2,%3}, [%4];"
                        : "=r"(r0), "=r"(r1), "=r"(r2), "=r"(r3) : "r"(addr));
                    b[nb * 2][0] = r0;     b[nb * 2][1] = r1;
                    b[nb * 2 + 1][0] = r2; b[nb * 2 + 1][1] = r3;
                }
            }
#pragma unroll
            for (int mt = 0; mt < 4; ++mt)
#pragma unroll
                for (int nt = 0; nt < 4; ++nt) {
                    asm volatile(
                        "mma.sync.aligned.m16n8k16.row.col.f32.bf16.bf16.f32 "
                        "{%0,%1,%2,%3}, {%4,%5,%6,%7}, {%8,%9}, {%0,%1,%2,%3};"
                        : "+f"(acc[mt][nt][0]), "+f"(acc[mt][nt][1]),
                          "+f"(acc[mt][nt][2]), "+f"(acc[mt][nt][3])
                        : "r"(a[mt][0]), "r"(a[mt][1]), "r"(a[mt][2]), "r"(a[mt][3]),
                          "r"(b[nt][0]), "r"(b[nt][1]));
                }
        }
        __syncthreads();
        buf = (buf + 1) % SST;
    }

    int g = lane >> 2, tg = lane & 3;
#pragma unroll
    for (int mt = 0; mt < 4; ++mt) {
#pragma unroll
        for (int nt = 0; nt < 4; ++nt) {
            int row = m0 + wm + mt * 16 + g;
            int col = n0 + wn + nt * 8 + tg * 2;
            *(float2*)(C + (size_t)row * N + col) =
                make_float2(acc[mt][nt][0], acc[mt][nt][1]);
            *(float2*)(C + (size_t)(row + 8) * N + col) =
                make_float2(acc[mt][nt][2], acc[mt][nt][3]);
        }
    }
}

// ---------------- fused QKV conv + SiLU + l2norm + kb (t-offset) ----------------
__global__ __launch_bounds__(256) void conv_qkvn_kernel(
    const float* __restrict__ x3,
    const float* __restrict__ cq, const float* __restrict__ ck,
    const float* __restrict__ cv, const float* __restrict__ beta,
    float* __restrict__ q, float* __restrict__ k,
    float* __restrict__ kb, float* __restrict__ v, int L, int t0)
{
    int t = blockIdx.x + t0;
    int b = t / L, l = t % L;
    int tid = threadIdx.x;
    int lane = tid & 31, wid = tid >> 5;
    int c = tid * 4;

    const float* wp[3] = {cq, ck, cv};
    float4 outv[3];
#pragma unroll
    for (int proj = 0; proj < 3; ++proj) {
        int cOff = proj * 1024 + c;
        float4 xv[4];
#pragma unroll
        for (int kk = 0; kk < 4; ++kk) {
            int ll = l - 3 + kk;
            xv[kk] = (ll >= 0) ? *(const float4*)&x3[((size_t)(b*L + ll))*3072 + cOff]
                               : make_float4(0.f, 0.f, 0.f, 0.f);
        }
        const float* w = wp[proj];
        float4 w0 = *(const float4*)&w[(c+0)*4];
        float4 w1 = *(const float4*)&w[(c+1)*4];
        float4 w2 = *(const float4*)&w[(c+2)*4];
        float4 w3 = *(const float4*)&w[(c+3)*4];
        float4 acc;
        acc.x = xv[0].x*w0.x + xv[1].x*w0.y + xv[2].x*w0.z + xv[3].x*w0.w;
        acc.y = xv[0].y*w1.x + xv[1].y*w1.y + xv[2].y*w1.z + xv[3].y*w1.w;
        acc.z = xv[0].z*w2.x + xv[1].z*w2.y + xv[2].z*w2.z + xv[3].z*w2.w;
        acc.w = xv[0].w*w3.x + xv[1].w*w3.y + xv[2].w*w3.z + xv[3].w*w3.w;
        acc.x = acc.x / (1.f + expf(-acc.x));
        acc.y = acc.y / (1.f + expf(-acc.y));
        acc.z = acc.z / (1.f + expf(-acc.z));
        acc.w = acc.w / (1.f + expf(-acc.w));
        outv[proj] = acc;
    }
    *(float4*)&v[(size_t)t*HID + c] = outv[2];

    float4 qa = outv[0], ka = outv[1];
    float sq = qa.x*qa.x + qa.y*qa.y + qa.z*qa.z + qa.w*qa.w;
    float sk = ka.x*ka.x + ka.y*ka.y + ka.z*ka.z + ka.w*ka.w;
#pragma unroll
    for (int off = 16; off; off >>= 1) {
        sq += __shfl_down_sync(0xffffffff, sq, off);
        sk += __shfl_down_sync(0xffffffff, sk, off);
    }
    __shared__ float pq[8], pk[8];
    if (lane == 0) { pq[wid] = sq; pk[wid] = sk; }
    __syncthreads();
    int h = tid >> 6;
    float sumq = pq[h*2] + pq[h*2+1];
    float sumk = pk[h*2] + pk[h*2+1];
    float rq = rsqrtf(sumq + 1e-6f);
    float rk = rsqrtf(sumk + 1e-6f);
    float bb = beta[t*NH + h];
    float4 qn = make_float4(qa.x*rq, qa.y*rq, qa.z*rq, qa.w*rq);
    float4 kn = make_float4(ka.x*rk, ka.y*rk, ka.z*rk, ka.w*rk);
    float4 kbv = make_float4(kn.x*bb, kn.y*bb, kn.z*bb, kn.w*bb);
    *(float4*)&q [(size_t)t*HID + c] = qn;
    *(float4*)&k [(size_t)t*HID + c] = kn;
    *(float4*)&kb[(size_t)t*HID + c] = kbv;
}

// ---------------- fused FIR conv (tile-offset) ----------------------------------
__global__ __launch_bounds__(256) void fir_kernel(
    const float* __restrict__ V, const float* __restrict__ fs,
    const float* __restrict__ fl, float* __restrict__ LS,
    float* __restrict__ LL, int L, int tt0)
{
    __shared__ float xs[127*64];
    int ct = blockIdx.x;
    int tt = blockIdx.y + tt0;
    int c0 = ct * 64;
    int t0 = tt * 64;
    int b = t0 / L;
    int l0 = t0 - b * L;
    int tid = threadIdx.x;

    for (int idx = tid; idx < 127*64; idx += 256) {
        int row = idx >> 6, c = idx & 63;
        int l = l0 - 63 + row;
        xs[idx] = (l >= 0) ? V[((size_t)(b*L + l))*HID + c0 + c] : 0.f;
    }

    int c = tid & 63;
    int tg = tid >> 6;
    int cg = c0 + c;
    float wl[64];
#pragma unroll
    for (int kk = 0; kk < 64; ++kk) wl[kk] = fl[cg*64 + kk];
    float ws[5];
#pragma unroll
    for (int kk = 0; kk < 5; ++kk) ws[kk] = fs[cg*5 + kk];
    __syncthreads();

    for (int j = 0; j < 16; ++j) {
        int jj = tg*16 + j;
        float accl = 0.f, accs = 0.f;
#pragma unroll
        for (int kk = 0; kk < 64; ++kk) accl += xs[(jj+kk)*64 + c] * wl[kk];
#pragma unroll
        for (int kk = 0; kk < 5; ++kk) accs += xs[(jj+59+kk)*64 + c] * ws[kk];
        size_t o = ((size_t)(t0 + jj))*HID + cg;
        LL[o] = accl;
        LS[o] = accs;
    }
}

// ---------------- beta ------------------------------------------------------------
__global__ void beta_kernel(const float* __restrict__ hs, const float* __restrict__ Wb,
                            float* __restrict__ beta, int T)
{
    int gw = (blockIdx.x * blockDim.x + threadIdx.x) >> 5;
    int lane = threadIdx.x & 31;
    if (gw >= T * NH) return;
    int t = gw / NH, h = gw % NH;
    float s = 0.f;
    for (int r = lane; r < HID; r += 32) s += hs[(size_t)t*HID + r] * Wb[r*NH + h];
#pragma unroll
    for (int off = 16; off; off >>= 1) s += __shfl_down_sync(0xffffffff, s, off);
    if (lane == 0) beta[t*NH + h] = 1.f / (1.f + expf(-s));
}

// ---------------- per-chunk: attn inversion + u, w, attn_loc (cid offset, v4) ---
__global__ __launch_bounds__(256) void chunk_kernel(
    const float* __restrict__ Qn, const float* __restrict__ Kn,
    const float* __restrict__ KB, const float* __restrict__ V,
    const float* __restrict__ beta, float* __restrict__ U,
    float* __restrict__ Wbuf, float* __restrict__ Aloc, int L, int cid0)
{
    extern __shared__ float sm[];
    float* q_s  = sm;
    float* kn_s = q_s  + 32*QP;
    float* kb_s = kn_s + 32*QP;
    float* A    = kb_s + 32*QP;
    int nch = L / CHUNK;
    int cid = blockIdx.x + cid0;
    int ch = cid % nch;
    int h  = (cid / nch) & (NH - 1);
    int b  = cid / (nch * NH);
    int l0 = ch * CHUNK;
    int tid = threadIdx.x;
    int lane = tid & 31;
    int iw = tid >> 5;
    size_t base = ((size_t)(b*L + l0)) * HID + h*DK;

    // vectorized tile loads: 8 float4 per array per thread
#pragma unroll
    for (int it = 0; it < 8; ++it) {
        int idx = it * 256 + tid;
        int row = idx >> 6, cg4 = (idx & 63) * 4;
        size_t g = base + (size_t)row*HID + cg4;
        *(float4*)&q_s [row*QP + cg4] = *(const float4*)&Qn[g];
        *(float4*)&kn_s[row*QP + cg4] = *(const float4*)&Kn[g];
        *(float4*)&kb_s[row*QP + cg4] = *(const float4*)&KB[g];
    }
    __syncthreads();

    size_t abase = (size_t)cid * (CHUNK*CHUNK);
#pragma unroll
    for (int r = 0; r < 4; ++r) {
        int i = r*8 + iw, j = lane;
        float sA = 0.f, sL = 0.f;
#pragma unroll 8
        for (int dq = 0; dq < 64; ++dq) {
            float4 kn = *(float4*)&kn_s[j*QP + dq*4];
            float4 kbv = *(float4*)&kb_s[i*QP + dq*4];
            float4 qv = *(float4*)&q_s [i*QP + dq*4];
            sA += kbv.x*kn.x + kbv.y*kn.y + kbv.z*kn.z + kbv.w*kn.w;
            sL += qv.x*kn.x + qv.y*kn.y + qv.z*kn.z + qv.w*kn.w;
        }
        A[i*KTP + j] = (i > j) ? -sA : 0.f;
        Aloc[abase + i*32 + j] = (j <= i) ? sL : 0.f;
    }
    __syncthreads();

    if (tid < 32) {
        int j = tid;
        for (int i = 1; i < 32; ++i) {
            float s = 0.f;
            if (j < i) {
#pragma unroll
                for (int t2 = 0; t2 < 32; ++t2) s += A[i*KTP + t2] * A[t2*KTP + j];
            }
            __syncwarp();
            if (j < i) A[i*KTP + j] += s;
            __syncwarp();
        }
        A[j*KTP + j] += 1.f;
    }
    __syncthreads();

    // v*beta into q_s (vectorized)
#pragma unroll
    for (int it = 0; it < 8; ++it) {
        int idx = it * 256 + tid;
        int row = idx >> 6, cg4 = (idx & 63) * 4;
        float bb = beta[(b*L + l0 + row)*NH + h];
        float4 vv = *(const float4*)&V[base + (size_t)row*HID + cg4];
        *(float4*)&q_s[row*QP + cg4] =
            make_float4(vv.x*bb, vv.y*bb, vv.z*bb, vv.w*bb);
    }
    __syncthreads();

    float vc[32], kc[32];
#pragma unroll
    for (int t2 = 0; t2 < 32; ++t2) {
        vc[t2] = q_s [t2*QP + tid];
        kc[t2] = kb_s[t2*QP + tid];
    }

    for (int i = 0; i < 32; ++i) {
        float su = 0.f, sw = 0.f;
#pragma unroll
        for (int qq = 0; qq < 8; ++qq) {
            float4 a = *(float4*)&A[i*KTP + qq*4];
            su += a.x*vc[qq*4] + a.y*vc[qq*4+1] + a.z*vc[qq*4+2] + a.w*vc[qq*4+3];
            sw += a.x*kc[qq*4] + a.y*kc[qq*4+1] + a.z*kc[qq*4+2] + a.w*kc[qq*4+3];
        }
        U   [base + (size_t)i*HID + tid] = su;
        Wbuf[base + (size_t)i*HID + tid] = sw;
    }
}

// ---------------- sequential chunk scan: 128 CTAs, 16 cols each (v4 loads) ------
__global__ __launch_bounds__(256) void scan_kernel(
    const float* __restrict__ Qn, const float* __restrict__ Kn,
    const float* __restrict__ U,  const float* __restrict__ Wbuf,
    const float* __restrict__ Aloc, float* __restrict__ Dout, int L)
{
    extern __shared__ float sm[];
    float* Ssm_t = sm;
    float* q_s   = Ssm_t + NC*QP;
    float* w_s   = q_s   + 32*QP;
    float* k_t   = w_s   + 32*QP;
    float* al    = k_t   + 256*KTP;
    float* ul_t  = al    + 32*KTP;

    int cb = blockIdx.x;
    int bh = blockIdx.y;
    int b = bh >> 2, h = bh & 3;
    int tid = threadIdx.x;
    int c  = tid & (NC - 1);
    int gi = tid >> 4;
    int nch = L / CHUNK;

    float Sreg[16];
#pragma unroll
    for (int r = 0; r < 16; ++r) Sreg[r] = 0.f;

    for (int ch = 0; ch < nch; ++ch) {
        int l0 = ch * CHUNK;
        size_t base = ((size_t)(b*L + l0)) * HID + h*DK;

#pragma unroll
        for (int r = 0; r < 16; ++r) Ssm_t[c*QP + r*16 + gi] = Sreg[r];
        // vectorized tile loads
#pragma unroll
        for (int it = 0; it < 8; ++it) {
            int idx = it * 256 + tid;
            int row = idx >> 6, cg4 = (idx & 63) * 4;
            size_t g = base + (size_t)row*HID + cg4;
            *(float4*)&q_s[row*QP + cg4] = *(const float4*)&Qn[g];
            *(float4*)&w_s[row*QP + cg4] = *(const float4*)&Wbuf[g];
            float4 kv = *(const float4*)&Kn[g];
            k_t[(cg4+0)*KTP + row] = kv.x;
            k_t[(cg4+1)*KTP + row] = kv.y;
            k_t[(cg4+2)*KTP + row] = kv.z;
            k_t[(cg4+3)*KTP + row] = kv.w;
        }
        size_t abase = (size_t)((b*NH + h)*nch + ch) * 1024;
#pragma unroll
        for (int e0 = 0; e0 < 4; ++e0) {
            int e = e0*256 + tid;
            al[(e >> 5)*KTP + (e & 31)] = Aloc[abase + e];
        }

        float uacc[2], oacc[2] = {0.f, 0.f};
#pragma unroll
        for (int r2 = 0; r2 < 2; ++r2)
            uacc[r2] = U[((size_t)(b*L + l0 + (r2*16 + gi)))*HID + h*DV + cb*NC + c];
        __syncthreads();

#pragma unroll 4
        for (int dq = 0; dq < 64; ++dq) {
            float4 sv = *(float4*)&Ssm_t[c*QP + dq*4];
#pragma unroll
            for (int r2 = 0; r2 < 2; ++r2) {
                int i = r2*16 + gi;
                float4 wv = *(float4*)&w_s[i*QP + dq*4];
                float4 qv = *(float4*)&q_s[i*QP + dq*4];
                uacc[r2] -= wv.x*sv.x + wv.y*sv.y + wv.z*sv.z + wv.w*sv.w;
                oacc[r2] += qv.x*sv.x + qv.y*sv.y + qv.z*sv.z + qv.w*sv.w;
            }
        }
#pragma unroll
        for (int r2 = 0; r2 < 2; ++r2) ul_t[c*KTP + r2*16 + gi] = uacc[r2];
        __syncthreads();

        float ulreg[32];
#pragma unroll
        for (int qq = 0; qq < 8; ++qq) {
            float4 t4 = *(float4*)&ul_t[c*KTP + qq*4];
            ulreg[qq*4] = t4.x; ulreg[qq*4+1] = t4.y;
            ulreg[qq*4+2] = t4.z; ulreg[qq*4+3] = t4.w;
        }

#pragma unroll
        for (int qq = 0; qq < 8; ++qq) {
#pragma unroll
            for (int r2 = 0; r2 < 2; ++r2) {
                int i = r2*16 + gi;
                float4 av = *(float4*)&al[i*KTP + qq*4];
                oacc[r2] += av.x*ulreg[qq*4] + av.y*ulreg[qq*4+1]
                          + av.z*ulreg[qq*4+2] + av.w*ulreg[qq*4+3];
            }
        }
#pragma unroll
        for (int r2 = 0; r2 < 2; ++r2)
            Dout[((size_t)(b*L + l0 + (r2*16 + gi)))*HID + h*DV + cb*NC + c] = oacc[r2];

#pragma unroll
        for (int qq = 0; qq < 8; ++qq) {
#pragma unroll
            for (int r = 0; r < 16; ++r) {
                float4 kv = *(float4*)&k_t[(r*16 + gi)*KTP + qq*4];
                Sreg[r] += kv.x*ulreg[qq*4] + kv.y*ulreg[qq*4+1]
                         + kv.z*ulreg[qq*4+2] + kv.w*ulreg[qq*4+3];
            }
        }
        __syncthreads();
    }
}

// ---------------- fused stats + gate MLP + softmax + mix + RMSNorm + split ------
__global__ __launch_bounds__(256) void gsm_kernel(
    const float* __restrict__ LS, const float* __restrict__ LL,
    const float* __restrict__ DEL, const float* __restrict__ V,
    const float* __restrict__ G1,
    const float* __restrict__ w1, const float* __restrict__ b1,
    const float* __restrict__ w2, const float* __restrict__ b2,
    const float* __restrict__ lt, const float* __restrict__ onw,
    __nv_bfloat16* __restrict__ A2)
{
    int t = blockIdx.x;
    int tid = threadIdx.x;
    int lane = tid & 31, wid = tid >> 5;
    int h = tid >> 6;
    int cin = (tid & 63) * 4;

    size_t base = (size_t)t*1024 + h*256 + cin;
    float4 xs0 = *(const float4*)&LS [base];
    float4 xs1 = *(const float4*)&LL [base];
    float4 xs2 = *(const float4*)&DEL[base];
    float4 xs3 = *(const float4*)&V  [base];

    __shared__ float wstat[8][12];
    {
        float4 xs[4] = {xs0, xs1, xs2, xs3};
#pragma unroll
        for (int sig = 0; sig < 4; ++sig) {
            float4 x = xs[sig];
            float s1 = x.x + x.y + x.z + x.w;
            float s2 = x.x*x.x + x.y*x.y + x.z*x.z + x.w*x.w;
            float s3 = fabsf(x.x) + fabsf(x.y) + fabsf(x.z) + fabsf(x.w);
#pragma unroll
            for (int off = 16; off; off >>= 1) {
                s1 += __shfl_down_sync(0xffffffff, s1, off);
                s2 += __shfl_down_sync(0xffffffff, s2, off);
                s3 += __shfl_down_sync(0xffffffff, s3, off);
            }
            if (lane == 0) {
                wstat[wid][sig*3+0] = s1;
                wstat[wid][sig*3+1] = s2;
                wstat[wid][sig*3+2] = s3;
            }
        }
    }
    __syncthreads();

    __shared__ float st[4][16];
    if (tid < 64) {
        int hh = tid >> 4, idx = tid & 15, sig = idx >> 2, which = idx & 3;
        float s1 = wstat[hh*2][sig*3+0] + wstat[hh*2+1][sig*3+0];
        float s2 = wstat[hh*2][sig*3+1] + wstat[hh*2+1][sig*3+1];
        float s3 = wstat[hh*2][sig*3+2] + wstat[hh*2+1][sig*3+2];
        float mean = s1 / 256.f;
        float val;
        if (which == 0)      val = mean;
        else if (which == 1) val = s2 / 256.f - mean*mean;
        else if (which == 2) val = s3 / 256.f;
        else                 val = sqrtf(s2);
        st[hh][idx] = val;
    }
    __syncthreads();

    float p[4][4];
#pragma unroll
    for (int hh = 0; hh < 4; ++hh)
#pragma unroll
        for (int cc = 0; cc < 4; ++cc) p[hh][cc] = 0.f;

#pragma unroll
    for (int jj = 0; jj < 4; ++jj) {
        int j = jj*256 + tid;
        float xb = G1[(size_t)t*1024 + j] + b1[j];
        float w1v[16];
#pragma unroll
        for (int s = 0; s < 16; ++s) w1v[s] = w1[(size_t)(1024 + s)*1024 + j];
        float4 w2v = *(const float4*)&w2[j*4];
#pragma unroll
        for (int hh = 0; hh < 4; ++hh) {
            float x = xb;
#pragma unroll
            for (int s = 0; s < 16; ++s) x += st[hh][s] * w1v[s];
            float g = 0.5f * x * (1.f + erff(x * 0.70710678118654752f));
            p[hh][0] += g * w2v.x; p[hh][1] += g * w2v.y;
            p[hh][2] += g * w2v.z; p[hh][3] += g * w2v.w;
        }
    }
#pragma unroll
    for (int hh = 0; hh < 4; ++hh)
#pragma unroll
        for (int cc = 0; cc < 4; ++cc) {
            float vsum = p[hh][cc];
#pragma unroll
            for (int off = 16; off; off >>= 1)
                vsum += __shfl_down_sync(0xffffffff, vsum, off);
            p[hh][cc] = vsum;
        }
    __shared__ float red[8][16];
    if (lane == 0) {
#pragma unroll
        for (int hh = 0; hh < 4; ++hh)
#pragma unroll
            for (int cc = 0; cc < 4; ++cc) red[wid][hh*4+cc] = p[hh][cc];
    }
    __syncthreads();

    __shared__ float probs[4][4];
    if (tid < 4) {
        float l[4];
#pragma unroll
        for (int cc = 0; cc < 4; ++cc) {
            float s = 0.f;
#pragma unroll
            for (int wdx = 0; wdx < 8; ++wdx) s += red[wdx][tid*4+cc];
            l[cc] = s + b2[cc];
        }
        float inv_t = expf(-lt[tid]);
#pragma unroll
        for (int cc = 0; cc < 4; ++cc) l[cc] *= inv_t;
        float m = fmaxf(fmaxf(l[0], l[1]), fmaxf(l[2], l[3]));
        float e[4], ssum = 0.f;
#pragma unroll
        for (int cc = 0; cc < 4; ++cc) { e[cc] = expf(l[cc] - m); ssum += e[cc]; }
#pragma unroll
        for (int cc = 0; cc < 4; ++cc) probs[tid][cc] = 0.05f + 0.8f * (e[cc] / ssum);
    }
    __syncthreads();

    float p0 = probs[h][0], p1 = probs[h][1], p2 = probs[h][2], p3 = probs[h][3];
    float4 o;
    o.x = p0*xs0.x + p1*xs1.x + p2*xs2.x + p3*xs3.x;
    o.y = p0*xs0.y + p1*xs1.y + p2*xs2.y + p3*xs3.y;
    o.z = p0*xs0.z + p1*xs1.z + p2*xs2.z + p3*xs3.z;
    o.w = p0*xs0.w + p1*xs1.w + p2*xs2.w + p3*xs3.w;
    float sq = o.x*o.x + o.y*o.y + o.z*o.z + o.w*o.w;
#pragma unroll
    for (int off = 16; off; off >>= 1) sq += __shfl_down_sync(0xffffffff, sq, off);
    __shared__ float psq[8];
    if (lane == 0) psq[wid] = sq;
    __syncthreads();
    float ms = (psq[h*2] + psq[h*2+1]) / 256.f;
    float r = rsqrtf(ms + 1e-5f);
    float4 ow = *(const float4*)&onw[cin];
    float ov[4] = {o.x*r*ow.x, o.y*r*ow.y, o.z*r*ow.z, o.w*r*ow.w};

    int kk = h*256 + cin;
    __nv_bfloat16 hib[4]; float lob[4];
#pragma unroll
    for (int i = 0; i < 4; ++i) {
        hib[i] = __float2bfloat16(ov[i]);
        lob[i] = ov[i] - __bfloat162float(hib[i]);
    }
    *(uint2*)&A2[(size_t)t*2048 + kk] = *(uint2*)hib;
    __nv_bfloat16 lo16[4];
#pragma unroll
    for (int i = 0; i < 4; ++i) lo16[i] = __float2bfloat16(lob[i]);
    *(uint2*)&A2[(size_t)t*2048 + 1024 + kk] = *(uint2*)lo16;
}

// ---------------- launch ----------------------------------------------------------
extern "C" void kernel_launch(void* const* d_in, const int* in_sizes, int n_in,
                              void* d_out, int out_size)
{
    const float* hs = (const float*)d_in[0];
    const float* Wq = (const float*)d_in[1];
    const float* Wk = (const float*)d_in[2];
    const float* Wv = (const float*)d_in[3];
    const float* Wb = (const float*)d_in[4];
    const float* cq = (const float*)d_in[5];
    const float* ck = (const float*)d_in[6];
    const float* cv = (const float*)d_in[7];
    const float* fs = (const float*)d_in[8];
    const float* fl = (const float*)d_in[9];
    const float* w1 = (const float*)d_in[10];
    const float* b1 = (const float*)d_in[11];
    const float* w2 = (const float*)d_in[12];
    const float* b2 = (const float*)d_in[13];
    const float* lt = (const float*)d_in[14];
    const float* onw= (const float*)d_in[15];
    const float* Wo = (const float*)d_in[16];

    const int T = in_sizes[0] / HID;
    const int B = 2;
    const int L = T / B;
    const int TH = T / 2;            // per-batch rows

    float *tmp3, *q, *k, *v, *kb, *u, *w, *del, *ls, *ll, *g1, *aloc, *beta;
    __nv_bfloat16 *a2, *bth, *btl, *bthg, *btlg, *btho, *btlo;
    cudaGetSymbolAddress((void**)&tmp3, g_tmp3);
    cudaGetSymbolAddress((void**)&q,    g_q);
    cudaGetSymbolAddress((void**)&k,    g_k);
    cudaGetSymbolAddress((void**)&v,    g_v);
    cudaGetSymbolAddress((void**)&kb,   g_kb);
    cudaGetSymbolAddress((void**)&u,    g_u);
    cudaGetSymbolAddress((void**)&w,    g_w);
    cudaGetSymbolAddress((void**)&del,  g_del);
    cudaGetSymbolAddress((void**)&ls,   g_ls);
    cudaGetSymbolAddress((void**)&ll,   g_ll);
    cudaGetSymbolAddress((void**)&g1,   g_g1);
    cudaGetSymbolAddress((void**)&aloc, g_aloc);
    cudaGetSymbolAddress((void**)&beta, g_beta);
    cudaGetSymbolAddress((void**)&a2,   g_a2);
    cudaGetSymbolAddress((void**)&bth,  g_bth);
    cudaGetSymbolAddress((void**)&btl,  g_btl);
    cudaGetSymbolAddress((void**)&bthg, g_bthg);
    cudaGetSymbolAddress((void**)&btlg, g_btlg);
    cudaGetSymbolAddress((void**)&btho, g_btho);
    cudaGetSymbolAddress((void**)&btlo, g_btlo);

    static cudaStream_t s1 = 0, s2 = 0, s3 = 0;
    static cudaEvent_t evS = 0, evA = 0, evB = 0, evW = 0, evG = 0,
                       evC0 = 0, evC1 = 0, evK0 = 0, evF = 0;
    if (!s1) {
        cudaStreamCreateWithFlags(&s1, cudaStreamNonBlocking);
        cudaStreamCreateWithFlags(&s2, cudaStreamNonBlocking);
        cudaStreamCreateWithFlags(&s3, cudaStreamNonBlocking);
        cudaEventCreateWithFlags(&evS, cudaEventDisableTiming);
        cudaEventCreateWithFlags(&evA, cudaEventDisableTiming);
        cudaEventCreateWithFlags(&evB, cudaEventDisableTiming);
        cudaEventCreateWithFlags(&evW, cudaEventDisableTiming);
        cudaEventCreateWithFlags(&evG, cudaEventDisableTiming);
        cudaEventCreateWithFlags(&evC0, cudaEventDisableTiming);
        cudaEventCreateWithFlags(&evC1, cudaEventDisableTiming);
        cudaEventCreateWithFlags(&evK0, cudaEventDisableTiming);
        cudaEventCreateWithFlags(&evF, cudaEventDisableTiming);
    }

    dim3 bt_grid(HID/32, HID/32);
    dim3 bt_blk(32, 8);
    int nsplit = (T*HID + 255) / 256;
    int nch = L / CHUNK;

    const int GEMM_SMEM = SST * GSTAGE;
    cudaFuncSetAttribute(gemm_mma, cudaFuncAttributeMaxDynamicSharedMemorySize, GEMM_SMEM);
    size_t chunk_smem = (size_t)(3*32*QP + 32*KTP) * 4;
    size_t scan_smem  = (size_t)(NC*QP + 2*32*QP + 256*KTP + 32*KTP + NC*KTP) * 4;
    cudaFuncSetAttribute(chunk_kernel, cudaFuncAttributeMaxDynamicSharedMemorySize, (int)chunk_smem);
    cudaFuncSetAttribute(scan_kernel,  cudaFuncAttributeMaxDynamicSharedMemorySize, (int)scan_smem);

    // ---- fork point ----
    cudaEventRecord(evS, 0);

    // s3: beta
    cudaStreamWaitEvent(s3, evS, 0);
    beta_kernel<<<(T*NH + 7) / 8, 256, 0, s3>>>(hs, Wb, beta, T);
    cudaEventRecord(evB, s3);

    // s2: QKV weight splits
    cudaStreamWaitEvent(s2, evS, 0);
    bsplit_kernel<<<bt_grid, bt_blk, 0, s2>>>(Wq, bth,             btl,             HID, HID);
    bsplit_kernel<<<bt_grid, bt_blk, 0, s2>>>(Wk, bth + HID*HID,   btl + HID*HID,   HID, HID);
    bsplit_kernel<<<bt_grid, bt_blk, 0, s2>>>(Wv, bth + 2*HID*HID, btl + 2*HID*HID, HID, HID);
    cudaEventRecord(evW, s2);

    // stream0: split hs
    asplit_kernel<<<nsplit, 256>>>(hs, a2, HID, T*HID);
    cudaEventRecord(evA, 0);

    // s1: gate GEMM + Wo split
    cudaStreamWaitEvent(s1, evS, 0);
    bsplit_kernel<<<bt_grid, bt_blk, 0, s1>>>(w1, bthg, btlg, HID, HID);
    cudaStreamWaitEvent(s1, evA, 0);
    {
        dim3 gg(HID/BN, T/BM);
        gemm_mma<<<gg, 256, GEMM_SMEM, s1>>>(a2, bthg, btlg, g1, T, HID, HID);
    }
    bsplit_kernel<<<bt_grid, bt_blk, 0, s1>>>(Wo, btho, btlo, HID, HID);
    cudaEventRecord(evG, s1);

    // stream0: QKV GEMM batch 0 + conv0
    cudaStreamWaitEvent(0, evW, 0);
    {
        dim3 gg(3*HID/BN, TH/BM);
        gemm_mma<<<gg, 256, GEMM_SMEM>>>(a2, bth, btl, tmp3, TH, 3*HID, HID);
    }
    cudaStreamWaitEvent(0, evB, 0);
    conv_qkvn_kernel<<<TH, 256>>>(tmp3, cq, ck, cv, beta, q, k, kb, v, L, 0);
    cudaEventRecord(evC0, 0);

    // s2: chunk(b0) overlapped with batch-1 GEMM
    cudaStreamWaitEvent(s2, evC0, 0);
    chunk_kernel<<<NH*nch, 256, chunk_smem, s2>>>(q, k, kb, v, beta, u, w, aloc, L, 0);
    cudaEventRecord(evK0, s2);

    // s3: fir(b0) overlapped
    cudaStreamWaitEvent(s3, evC0, 0);
    fir_kernel<<<dim3(HID/64, TH/64), 256, 0, s3>>>(v, fs, fl, ls, ll, L, 0);

    // stream0: QKV GEMM batch 1 + conv1
    {
        dim3 gg(3*HID/BN, TH/BM);
        gemm_mma<<<gg, 256, GEMM_SMEM>>>(a2 + (size_t)TH*2*HID, bth, btl,
                                         tmp3 + (size_t)TH*3*HID, TH, 3*HID, HID);
    }
    conv_qkvn_kernel<<<TH, 256>>>(tmp3, cq, ck, cv, beta, q, k, kb, v, L, TH);
    cudaEventRecord(evC1, 0);

    // s3: fir(b1)
    cudaStreamWaitEvent(s3, evC1, 0);
    fir_kernel<<<dim3(HID/64, TH/64), 256, 0, s3>>>(v, fs, fl, ls, ll, L, TH/64);
    cudaEventRecord(evF, s3);

    // stream0: chunk(b1) then scan (after chunk b0)
    chunk_kernel<<<NH*nch, 256, chunk_smem, 0>>>(q, k, kb, v, beta, u, w, aloc, L, NH*nch);
    cudaStreamWaitEvent(0, evK0, 0);
    scan_kernel<<<dim3(DV/NC, B*NH), 256, scan_smem, 0>>>(q, k, u, w, aloc, del, L);

    // join + fused epilogue
    cudaStreamWaitEvent(0, evF, 0);
    cudaStreamWaitEvent(0, evG, 0);
    gsm_kernel<<<T, 256>>>(ls, ll, del, v, g1, w1, b1, w2, b2, lt, onw, a2);
    {
        dim3 gg(HID/BN, T/BM);
        gemm_mma<<<gg, 256, GEMM_SMEM>>>(a2, btho, btlo, (float*)d_out, T, HID, HID);
    }
}

// round 13
// speedup vs baseline: 1.0096x; 1.0096x over previous
#include <cuda_runtime.h>
#include <cuda_bf16.h>
#include <math.h>
#include <stdint.h>

#define HID 1024
#define NH 4
#define DK 256
#define DV 256
#define CHUNK 32
#define TMAX 8192
#define QP 260
#define KTP 36
#define NC 16

// ---------------- scratch ----------------
__device__ float g_tmp3 [TMAX*3*HID];
__device__ float g_q    [TMAX*HID];
__device__ float g_k    [TMAX*HID];
__device__ float g_v    [TMAX*HID];
__device__ float g_kb   [TMAX*HID];
__device__ float g_u    [TMAX*HID];
__device__ float g_w    [TMAX*HID];
__device__ float g_del  [TMAX*HID];
__device__ float g_ls   [TMAX*HID];
__device__ float g_ll   [TMAX*HID];
__device__ float g_g1   [TMAX*HID];
__device__ float g_aloc [TMAX*NH*CHUNK];
__device__ float g_beta [TMAX*NH];
__device__ __nv_bfloat16 g_a2 [TMAX*2*HID];
__device__ __nv_bfloat16 g_bth[3*HID*HID];
__device__ __nv_bfloat16 g_btl[3*HID*HID];
__device__ __nv_bfloat16 g_bthg[HID*HID];
__device__ __nv_bfloat16 g_btlg[HID*HID];
__device__ __nv_bfloat16 g_btho[HID*HID];
__device__ __nv_bfloat16 g_btlo[HID*HID];

__device__ __forceinline__ uint32_t smem_u32(const void* p) {
    uint32_t a;
    asm("{ .reg .u64 t; cvta.to.shared.u64 t, %1; cvt.u32.u64 %0, t; }" : "=r"(a) : "l"(p));
    return a;
}
__device__ __forceinline__ void cp16(uint32_t dst, const void* src) {
    asm volatile("cp.async.cg.shared.global [%0], [%1], 16;" :: "r"(dst), "l"(src));
}

// ---------------- precision-split prep ----------------
__global__ void asplit_kernel(const float* __restrict__ X,
                              __nv_bfloat16* __restrict__ A2, int K, int total) {
    int idx = blockIdx.x * blockDim.x + threadIdx.x;
    if (idx >= total) return;
    int m = idx / K, kk = idx - m * K;
    float v = X[idx];
    __nv_bfloat16 hi = __float2bfloat16(v);
    float r = v - __bfloat162float(hi);
    A2[(size_t)m * 2 * K + kk]     = hi;
    A2[(size_t)m * 2 * K + K + kk] = __float2bfloat16(r);
}

__global__ void bsplit_kernel(const float* __restrict__ W,
                              __nv_bfloat16* __restrict__ Bh,
                              __nv_bfloat16* __restrict__ Bl, int K, int N) {
    __shared__ float t[32][33];
    int bn = blockIdx.x * 32, bk = blockIdx.y * 32;
    int x = threadIdx.x, y = threadIdx.y;
    for (int i = y; i < 32; i += 8) t[i][x] = W[(size_t)(bk + i) * N + bn + x];
    __syncthreads();
    for (int i = y; i < 32; i += 8) {
        float v = t[x][i];
        __nv_bfloat16 hi = __float2bfloat16(v);
        float r = v - __bfloat162float(hi);
        Bh[(size_t)(bn + i) * K + bk + x] = hi;
        Bl[(size_t)(bn + i) * K + bk + x] = __float2bfloat16(r);
    }
}

// ---------------- bf16 mma.sync GEMM (3-term split), BK=64, 3-stage -------------
#define BM 128
#define BN 128
#define BK 64
#define APITCH 72
#define ASTAGE (BM * APITCH * 2)
#define GSTAGE (2 * ASTAGE)
#define SST 3

__global__ __launch_bounds__(256) void gemm_mma(
    const __nv_bfloat16* __restrict__ A2, const __nv_bfloat16* __restrict__ Bh,
    const __nv_bfloat16* __restrict__ Bl, float* __restrict__ C,
    int M, int N, int K)
{
    extern __shared__ __align__(16) char gsm[];
    uint32_t sb = smem_u32(gsm);

    const int tid = threadIdx.x;
    const int wid = tid >> 5, lane = tid & 31;
    const int m0 = blockIdx.y * BM, n0 = blockIdx.x * BN;
    const int wm = (wid >> 2) * 64, wn = (wid & 3) * 32;

    const int KBn = K / BK;
    const int NB = 3 * KBn;
    const size_t sA = (size_t)2 * K;

    auto load_stage = [&](int kb, int buf) {
        int seg = kb / KBn;
        int kk = (kb - seg * KBn) * BK;
        const __nv_bfloat16* Ap = A2 + (seg == 1 ? (size_t)K : 0) + kk;
        const __nv_bfloat16* Bp = ((seg == 2) ? Bl : Bh) + kk;
        uint32_t a_s = sb + (uint32_t)buf * GSTAGE;
        uint32_t b_s = a_s + ASTAGE;
#pragma unroll
        for (int i = 0; i < 4; ++i) {
            int idx = i * 256 + tid;
            int row = idx >> 3, ch = idx & 7;
            cp16(a_s + (uint32_t)(row * APITCH + ch * 8) * 2,
                 Ap + (size_t)(m0 + row) * sA + ch * 8);
            cp16(b_s + (uint32_t)(row * APITCH + ch * 8) * 2,
                 Bp + (size_t)(n0 + row) * K + ch * 8);
        }
    };

    float acc[4][4][4];
#pragma unroll
    for (int mt = 0; mt < 4; ++mt)
#pragma unroll
        for (int nt = 0; nt < 4; ++nt)
#pragma unroll
            for (int e = 0; e < 4; ++e) acc[mt][nt][e] = 0.f;

    load_stage(0, 0);
    asm volatile("cp.async.commit_group;" ::: "memory");
    load_stage(1, 1);
    asm volatile("cp.async.commit_group;" ::: "memory");

    int buf = 0;
    for (int kb = 0; kb < NB; ++kb) {
        asm volatile("cp.async.wait_group 1;" ::: "memory");
        __syncthreads();
        if (kb + 2 < NB) load_stage(kb + 2, (buf + 2) % SST);
        asm volatile("cp.async.commit_group;" ::: "memory");

        uint32_t a_s = sb + (uint32_t)buf * GSTAGE;
        uint32_t b_s = a_s + ASTAGE;
#pragma unroll
        for (int kp = 0; kp < 4; ++kp) {
            uint32_t a[4][4], b[4][2];
            {
                int r_off = lane & 15;
                int c_off = kp * 16 + (lane >> 4) * 8;
#pragma unroll
                for (int mt = 0; mt < 4; ++mt) {
                    uint32_t addr = a_s + (uint32_t)((wm + mt * 16 + r_off) * APITCH + c_off) * 2;
                    asm volatile("ldmatrix.sync.aligned.m8n8.x4.shared.b16 {%0,%1,%2,%3}, [%4];"
                        : "=r"(a[mt][0]), "=r"(a[mt][1]), "=r"(a[mt][2]), "=r"(a[mt][3])
                        : "r"(addr));
                }
            }
            {
                int n_off = (lane & 7) + (lane >> 4) * 8;
                int c_off = kp * 16 + ((lane >> 3) & 1) * 8;
#pragma unroll
                for (int nb = 0; nb < 2; ++nb) {
                    uint32_t r0, r1, r2, r3;
                    uint32_t addr = b_s + (uint32_t)((wn + nb * 16 + n_off) * APITCH + c_off) * 2;
                    asm volatile("ldmatrix.sync.aligned.m8n8.x4.shared.b16 {%0,%1,%2,%3}, [%4];"
                        : "=r"(r0), "=r"(r1), "=r"(r2), "=r"(r3) : "r"(addr));
                    b[nb * 2][0] = r0;     b[nb * 2][1] = r1;
                    b[nb * 2 + 1][0] = r2; b[nb * 2 + 1][1] = r3;
                }
            }
#pragma unroll
            for (int mt = 0; mt < 4; ++mt)
#pragma unroll
                for (int nt = 0; nt < 4; ++nt) {
                    asm volatile(
                        "mma.sync.aligned.m16n8k16.row.col.f32.bf16.bf16.f32 "
                        "{%0,%1,%2,%3}, {%4,%5,%6,%7}, {%8,%9}, {%0,%1,%2,%3};"
                        : "+f"(acc[mt][nt][0]), "+f"(acc[mt][nt][1]),
                          "+f"(acc[mt][nt][2]), "+f"(acc[mt][nt][3])
                        : "r"(a[mt][0]), "r"(a[mt][1]), "r"(a[mt][2]), "r"(a[mt][3]),
                          "r"(b[nt][0]), "r"(b[nt][1]));
                }
        }
        __syncthreads();
        buf = (buf + 1) % SST;
    }

    int g = lane >> 2, tg = lane & 3;
#pragma unroll
    for (int mt = 0; mt < 4; ++mt) {
#pragma unroll
        for (int nt = 0; nt < 4; ++nt) {
            int row = m0 + wm + mt * 16 + g;
            int col = n0 + wn + nt * 8 + tg * 2;
            *(float2*)(C + (size_t)row * N + col) =
                make_float2(acc[mt][nt][0], acc[mt][nt][1]);
            *(float2*)(C + (size_t)(row + 8) * N + col) =
                make_float2(acc[mt][nt][2], acc[mt][nt][3]);
        }
    }
}

// ---------------- fused QKV conv + SiLU + l2norm + kb ---------------------------
__global__ __launch_bounds__(256) void conv_qkvn_kernel(
    const float* __restrict__ x3,
    const float* __restrict__ cq, const float* __restrict__ ck,
    const float* __restrict__ cv, const float* __restrict__ beta,
    float* __restrict__ q, float* __restrict__ k,
    float* __restrict__ kb, float* __restrict__ v, int L)
{
    int t = blockIdx.x;
    int b = t / L, l = t % L;
    int tid = threadIdx.x;
    int lane = tid & 31, wid = tid >> 5;
    int c = tid * 4;

    const float* wp[3] = {cq, ck, cv};
    float4 outv[3];
#pragma unroll
    for (int proj = 0; proj < 3; ++proj) {
        int cOff = proj * 1024 + c;
        float4 xv[4];
#pragma unroll
        for (int kk = 0; kk < 4; ++kk) {
            int ll = l - 3 + kk;
            xv[kk] = (ll >= 0) ? *(const float4*)&x3[((size_t)(b*L + ll))*3072 + cOff]
                               : make_float4(0.f, 0.f, 0.f, 0.f);
        }
        const float* w = wp[proj];
        float4 w0 = *(const float4*)&w[(c+0)*4];
        float4 w1 = *(const float4*)&w[(c+1)*4];
        float4 w2 = *(const float4*)&w[(c+2)*4];
        float4 w3 = *(const float4*)&w[(c+3)*4];
        float4 acc;
        acc.x = xv[0].x*w0.x + xv[1].x*w0.y + xv[2].x*w0.z + xv[3].x*w0.w;
        acc.y = xv[0].y*w1.x + xv[1].y*w1.y + xv[2].y*w1.z + xv[3].y*w1.w;
        acc.z = xv[0].z*w2.x + xv[1].z*w2.y + xv[2].z*w2.z + xv[3].z*w2.w;
        acc.w = xv[0].w*w3.x + xv[1].w*w3.y + xv[2].w*w3.z + xv[3].w*w3.w;
        acc.x = acc.x / (1.f + expf(-acc.x));
        acc.y = acc.y / (1.f + expf(-acc.y));
        acc.z = acc.z / (1.f + expf(-acc.z));
        acc.w = acc.w / (1.f + expf(-acc.w));
        outv[proj] = acc;
    }
    *(float4*)&v[(size_t)t*HID + c] = outv[2];

    float4 qa = outv[0], ka = outv[1];
    float sq = qa.x*qa.x + qa.y*qa.y + qa.z*qa.z + qa.w*qa.w;
    float sk = ka.x*ka.x + ka.y*ka.y + ka.z*ka.z + ka.w*ka.w;
#pragma unroll
    for (int off = 16; off; off >>= 1) {
        sq += __shfl_down_sync(0xffffffff, sq, off);
        sk += __shfl_down_sync(0xffffffff, sk, off);
    }
    __shared__ float pq[8], pk[8];
    if (lane == 0) { pq[wid] = sq; pk[wid] = sk; }
    __syncthreads();
    int h = tid >> 6;
    float sumq = pq[h*2] + pq[h*2+1];
    float sumk = pk[h*2] + pk[h*2+1];
    float rq = rsqrtf(sumq + 1e-6f);
    float rk = rsqrtf(sumk + 1e-6f);
    float bb = beta[t*NH + h];
    float4 qn = make_float4(qa.x*rq, qa.y*rq, qa.z*rq, qa.w*rq);
    float4 kn = make_float4(ka.x*rk, ka.y*rk, ka.z*rk, ka.w*rk);
    float4 kbv = make_float4(kn.x*bb, kn.y*bb, kn.z*bb, kn.w*bb);
    *(float4*)&q [(size_t)t*HID + c] = qn;
    *(float4*)&k [(size_t)t*HID + c] = kn;
    *(float4*)&kb[(size_t)t*HID + c] = kbv;
}

// ---------------- fused FIR conv (short K=5 + long K=64), smem-tiled ------------
__global__ __launch_bounds__(256) void fir_kernel(
    const float* __restrict__ V, const float* __restrict__ fs,
    const float* __restrict__ fl, float* __restrict__ LS,
    float* __restrict__ LL, int L)
{
    __shared__ float xs[127*64];
    int ct = blockIdx.x;
    int tt = blockIdx.y;
    int c0 = ct * 64;
    int t0 = tt * 64;
    int b = t0 / L;
    int l0 = t0 - b * L;
    int tid = threadIdx.x;

    for (int idx = tid; idx < 127*64; idx += 256) {
        int row = idx >> 6, c = idx & 63;
        int l = l0 - 63 + row;
        xs[idx] = (l >= 0) ? V[((size_t)(b*L + l))*HID + c0 + c] : 0.f;
    }

    int c = tid & 63;
    int tg = tid >> 6;
    int cg = c0 + c;
    float wl[64];
#pragma unroll
    for (int kk = 0; kk < 64; ++kk) wl[kk] = fl[cg*64 + kk];
    float ws[5];
#pragma unroll
    for (int kk = 0; kk < 5; ++kk) ws[kk] = fs[cg*5 + kk];
    __syncthreads();

    for (int j = 0; j < 16; ++j) {
        int jj = tg*16 + j;
        float accl = 0.f, accs = 0.f;
#pragma unroll
        for (int kk = 0; kk < 64; ++kk) accl += xs[(jj+kk)*64 + c] * wl[kk];
#pragma unroll
        for (int kk = 0; kk < 5; ++kk) accs += xs[(jj+59+kk)*64 + c] * ws[kk];
        size_t o = ((size_t)(t0 + jj))*HID + cg;
        LL[o] = accl;
        LS[o] = accs;
    }
}

// ---------------- beta ------------------------------------------------------------
__global__ void beta_kernel(const float* __restrict__ hs, const float* __restrict__ Wb,
                            float* __restrict__ beta, int T)
{
    int gw = (blockIdx.x * blockDim.x + threadIdx.x) >> 5;
    int lane = threadIdx.x & 31;
    if (gw >= T * NH) return;
    int t = gw / NH, h = gw % NH;
    float s = 0.f;
    for (int r = lane; r < HID; r += 32) s += hs[(size_t)t*HID + r] * Wb[r*NH + h];
#pragma unroll
    for (int off = 16; off; off >>= 1) s += __shfl_down_sync(0xffffffff, s, off);
    if (lane == 0) beta[t*NH + h] = 1.f / (1.f + expf(-s));
}

// ---------------- per-chunk: attn inversion + u, w, attn_loc (v4 loads) ---------
__global__ __launch_bounds__(256) void chunk_kernel(
    const float* __restrict__ Qn, const float* __restrict__ Kn,
    const float* __restrict__ KB, const float* __restrict__ V,
    const float* __restrict__ beta, float* __restrict__ U,
    float* __restrict__ Wbuf, float* __restrict__ Aloc, int L)
{
    extern __shared__ float sm[];
    float* q_s  = sm;
    float* kn_s = q_s  + 32*QP;
    float* kb_s = kn_s + 32*QP;
    float* A    = kb_s + 32*QP;
    int nch = L / CHUNK;
    int cid = blockIdx.x;
    int ch = cid % nch;
    int h  = (cid / nch) & (NH - 1);
    int b  = cid / (nch * NH);
    int l0 = ch * CHUNK;
    int tid = threadIdx.x;
    int lane = tid & 31;
    int iw = tid >> 5;
    size_t base = ((size_t)(b*L + l0)) * HID + h*DK;

    // vectorized tile loads: 8 float4 per array per thread
#pragma unroll
    for (int it = 0; it < 8; ++it) {
        int idx = it * 256 + tid;
        int row = idx >> 6, cg4 = (idx & 63) * 4;
        size_t g = base + (size_t)row*HID + cg4;
        *(float4*)&q_s [row*QP + cg4] = *(const float4*)&Qn[g];
        *(float4*)&kn_s[row*QP + cg4] = *(const float4*)&Kn[g];
        *(float4*)&kb_s[row*QP + cg4] = *(const float4*)&KB[g];
    }
    __syncthreads();

    size_t abase = (size_t)cid * (CHUNK*CHUNK);
#pragma unroll
    for (int r = 0; r < 4; ++r) {
        int i = r*8 + iw, j = lane;
        float sA = 0.f, sL = 0.f;
#pragma unroll 8
        for (int dq = 0; dq < 64; ++dq) {
            float4 kn = *(float4*)&kn_s[j*QP + dq*4];
            float4 kbv = *(float4*)&kb_s[i*QP + dq*4];
            float4 qv = *(float4*)&q_s [i*QP + dq*4];
            sA += kbv.x*kn.x + kbv.y*kn.y + kbv.z*kn.z + kbv.w*kn.w;
            sL += qv.x*kn.x + qv.y*kn.y + qv.z*kn.z + qv.w*kn.w;
        }
        A[i*KTP + j] = (i > j) ? -sA : 0.f;
        Aloc[abase + i*32 + j] = (j <= i) ? sL : 0.f;
    }
    __syncthreads();

    if (tid < 32) {
        int j = tid;
        for (int i = 1; i < 32; ++i) {
            float s = 0.f;
            if (j < i) {
#pragma unroll
                for (int t2 = 0; t2 < 32; ++t2) s += A[i*KTP + t2] * A[t2*KTP + j];
            }
            __syncwarp();
            if (j < i) A[i*KTP + j] += s;
            __syncwarp();
        }
        A[j*KTP + j] += 1.f;
    }
    __syncthreads();

    // v*beta into q_s (vectorized)
#pragma unroll
    for (int it = 0; it < 8; ++it) {
        int idx = it * 256 + tid;
        int row = idx >> 6, cg4 = (idx & 63) * 4;
        float bb = beta[(b*L + l0 + row)*NH + h];
        float4 vv = *(const float4*)&V[base + (size_t)row*HID + cg4];
        *(float4*)&q_s[row*QP + cg4] =
            make_float4(vv.x*bb, vv.y*bb, vv.z*bb, vv.w*bb);
    }
    __syncthreads();

    float vc[32], kc[32];
#pragma unroll
    for (int t2 = 0; t2 < 32; ++t2) {
        vc[t2] = q_s [t2*QP + tid];
        kc[t2] = kb_s[t2*QP + tid];
    }

    for (int i = 0; i < 32; ++i) {
        float su = 0.f, sw = 0.f;
#pragma unroll
        for (int qq = 0; qq < 8; ++qq) {
            float4 a = *(float4*)&A[i*KTP + qq*4];
            su += a.x*vc[qq*4] + a.y*vc[qq*4+1] + a.z*vc[qq*4+2] + a.w*vc[qq*4+3];
            sw += a.x*kc[qq*4] + a.y*kc[qq*4+1] + a.z*kc[qq*4+2] + a.w*kc[qq*4+3];
        }
        U   [base + (size_t)i*HID + tid] = su;
        Wbuf[base + (size_t)i*HID + tid] = sw;
    }
}

// ---------------- sequential chunk scan: 128 CTAs, 16 cols each (v4 loads) ------
__global__ __launch_bounds__(256) void scan_kernel(
    const float* __restrict__ Qn, const float* __restrict__ Kn,
    const float* __restrict__ U,  const float* __restrict__ Wbuf,
    const float* __restrict__ Aloc, float* __restrict__ Dout, int L)
{
    extern __shared__ float sm[];
    float* Ssm_t = sm;
    float* q_s   = Ssm_t + NC*QP;
    float* w_s   = q_s   + 32*QP;
    float* k_t   = w_s   + 32*QP;
    float* al    = k_t   + 256*KTP;
    float* ul_t  = al    + 32*KTP;

    int cb = blockIdx.x;
    int bh = blockIdx.y;
    int b = bh >> 2, h = bh & 3;
    int tid = threadIdx.x;
    int c  = tid & (NC - 1);
    int gi = tid >> 4;
    int nch = L / CHUNK;

    float Sreg[16];
#pragma unroll
    for (int r = 0; r < 16; ++r) Sreg[r] = 0.f;

    for (int ch = 0; ch < nch; ++ch) {
        int l0 = ch * CHUNK;
        size_t base = ((size_t)(b*L + l0)) * HID + h*DK;

#pragma unroll
        for (int r = 0; r < 16; ++r) Ssm_t[c*QP + r*16 + gi] = Sreg[r];
        // vectorized tile loads
#pragma unroll
        for (int it = 0; it < 8; ++it) {
            int idx = it * 256 + tid;
            int row = idx >> 6, cg4 = (idx & 63) * 4;
            size_t g = base + (size_t)row*HID + cg4;
            *(float4*)&q_s[row*QP + cg4] = *(const float4*)&Qn[g];
            *(float4*)&w_s[row*QP + cg4] = *(const float4*)&Wbuf[g];
            float4 kv = *(const float4*)&Kn[g];
            k_t[(cg4+0)*KTP + row] = kv.x;
            k_t[(cg4+1)*KTP + row] = kv.y;
            k_t[(cg4+2)*KTP + row] = kv.z;
            k_t[(cg4+3)*KTP + row] = kv.w;
        }
        size_t abase = (size_t)((b*NH + h)*nch + ch) * 1024;
#pragma unroll
        for (int e0 = 0; e0 < 4; ++e0) {
            int e = e0*256 + tid;
            al[(e >> 5)*KTP + (e & 31)] = Aloc[abase + e];
        }

        float uacc[2], oacc[2] = {0.f, 0.f};
#pragma unroll
        for (int r2 = 0; r2 < 2; ++r2)
            uacc[r2] = U[((size_t)(b*L + l0 + (r2*16 + gi)))*HID + h*DV + cb*NC + c];
        __syncthreads();

#pragma unroll 4
        for (int dq = 0; dq < 64; ++dq) {
            float4 sv = *(float4*)&Ssm_t[c*QP + dq*4];
#pragma unroll
            for (int r2 = 0; r2 < 2; ++r2) {
                int i = r2*16 + gi;
                float4 wv = *(float4*)&w_s[i*QP + dq*4];
                float4 qv = *(float4*)&q_s[i*QP + dq*4];
                uacc[r2] -= wv.x*sv.x + wv.y*sv.y + wv.z*sv.z + wv.w*sv.w;
                oacc[r2] += qv.x*sv.x + qv.y*sv.y + qv.z*sv.z + qv.w*sv.w;
            }
        }
#pragma unroll
        for (int r2 = 0; r2 < 2; ++r2) ul_t[c*KTP + r2*16 + gi] = uacc[r2];
        __syncthreads();

        float ulreg[32];
#pragma unroll
        for (int qq = 0; qq < 8; ++qq) {
            float4 t4 = *(float4*)&ul_t[c*KTP + qq*4];
            ulreg[qq*4] = t4.x; ulreg[qq*4+1] = t4.y;
            ulreg[qq*4+2] = t4.z; ulreg[qq*4+3] = t4.w;
        }

#pragma unroll
        for (int qq = 0; qq < 8; ++qq) {
#pragma unroll
            for (int r2 = 0; r2 < 2; ++r2) {
                int i = r2*16 + gi;
                float4 av = *(float4*)&al[i*KTP + qq*4];
                oacc[r2] += av.x*ulreg[qq*4] + av.y*ulreg[qq*4+1]
                          + av.z*ulreg[qq*4+2] + av.w*ulreg[qq*4+3];
            }
        }
#pragma unroll
        for (int r2 = 0; r2 < 2; ++r2)
            Dout[((size_t)(b*L + l0 + (r2*16 + gi)))*HID + h*DV + cb*NC + c] = oacc[r2];

#pragma unroll
        for (int qq = 0; qq < 8; ++qq) {
#pragma unroll
            for (int r = 0; r < 16; ++r) {
                float4 kv = *(float4*)&k_t[(r*16 + gi)*KTP + qq*4];
                Sreg[r] += kv.x*ulreg[qq*4] + kv.y*ulreg[qq*4+1]
                         + kv.z*ulreg[qq*4+2] + kv.w*ulreg[qq*4+3];
            }
        }
        __syncthreads();
    }
}

// ---------------- fused stats + gate MLP + softmax + mix + RMSNorm + split ------
__global__ __launch_bounds__(256) void gsm_kernel(
    const float* __restrict__ LS, const float* __restrict__ LL,
    const float* __restrict__ DEL, const float* __restrict__ V,
    const float* __restrict__ G1,
    const float* __restrict__ w1, const float* __restrict__ b1,
    const float* __restrict__ w2, const float* __restrict__ b2,
    const float* __restrict__ lt, const float* __restrict__ onw,
    __nv_bfloat16* __restrict__ A2)
{
    int t = blockIdx.x;
    int tid = threadIdx.x;
    int lane = tid & 31, wid = tid >> 5;
    int h = tid >> 6;
    int cin = (tid & 63) * 4;

    size_t base = (size_t)t*1024 + h*256 + cin;
    float4 xs0 = *(const float4*)&LS [base];
    float4 xs1 = *(const float4*)&LL [base];
    float4 xs2 = *(const float4*)&DEL[base];
    float4 xs3 = *(const float4*)&V  [base];

    __shared__ float wstat[8][12];
    {
        float4 xs[4] = {xs0, xs1, xs2, xs3};
#pragma unroll
        for (int sig = 0; sig < 4; ++sig) {
            float4 x = xs[sig];
            float s1 = x.x + x.y + x.z + x.w;
            float s2 = x.x*x.x + x.y*x.y + x.z*x.z + x.w*x.w;
            float s3 = fabsf(x.x) + fabsf(x.y) + fabsf(x.z) + fabsf(x.w);
#pragma unroll
            for (int off = 16; off; off >>= 1) {
                s1 += __shfl_down_sync(0xffffffff, s1, off);
                s2 += __shfl_down_sync(0xffffffff, s2, off);
                s3 += __shfl_down_sync(0xffffffff, s3, off);
            }
            if (lane == 0) {
                wstat[wid][sig*3+0] = s1;
                wstat[wid][sig*3+1] = s2;
                wstat[wid][sig*3+2] = s3;
            }
        }
    }
    __syncthreads();

    __shared__ float st[4][16];
    if (tid < 64) {
        int hh = tid >> 4, idx = tid & 15, sig = idx >> 2, which = idx & 3;
        float s1 = wstat[hh*2][sig*3+0] + wstat[hh*2+1][sig*3+0];
        float s2 = wstat[hh*2][sig*3+1] + wstat[hh*2+1][sig*3+1];
        float s3 = wstat[hh*2][sig*3+2] + wstat[hh*2+1][sig*3+2];
        float mean = s1 / 256.f;
        float val;
        if (which == 0)      val = mean;
        else if (which == 1) val = s2 / 256.f - mean*mean;
        else if (which == 2) val = s3 / 256.f;
        else                 val = sqrtf(s2);
        st[hh][idx] = val;
    }
    __syncthreads();

    float p[4][4];
#pragma unroll
    for (int hh = 0; hh < 4; ++hh)
#pragma unroll
        for (int cc = 0; cc < 4; ++cc) p[hh][cc] = 0.f;

#pragma unroll
    for (int jj = 0; jj < 4; ++jj) {
        int j = jj*256 + tid;
        float xb = G1[(size_t)t*1024 + j] + b1[j];
        float w1v[16];
#pragma unroll
        for (int s = 0; s < 16; ++s) w1v[s] = w1[(size_t)(1024 + s)*1024 + j];
        float4 w2v = *(const float4*)&w2[j*4];
#pragma unroll
        for (int hh = 0; hh < 4; ++hh) {
            float x = xb;
#pragma unroll
            for (int s = 0; s < 16; ++s) x += st[hh][s] * w1v[s];
            float g = 0.5f * x * (1.f + erff(x * 0.70710678118654752f));
            p[hh][0] += g * w2v.x; p[hh][1] += g * w2v.y;
            p[hh][2] += g * w2v.z; p[hh][3] += g * w2v.w;
        }
    }
#pragma unroll
    for (int hh = 0; hh < 4; ++hh)
#pragma unroll
        for (int cc = 0; cc < 4; ++cc) {
            float vsum = p[hh][cc];
#pragma unroll
            for (int off = 16; off; off >>= 1)
                vsum += __shfl_down_sync(0xffffffff, vsum, off);
            p[hh][cc] = vsum;
        }
    __shared__ float red[8][16];
    if (lane == 0) {
#pragma unroll
        for (int hh = 0; hh < 4; ++hh)
#pragma unroll
            for (int cc = 0; cc < 4; ++cc) red[wid][hh*4+cc] = p[hh][cc];
    }
    __syncthreads();

    __shared__ float probs[4][4];
    if (tid < 4) {
        float l[4];
#pragma unroll
        for (int cc = 0; cc < 4; ++cc) {
            float s = 0.f;
#pragma unroll
            for (int wdx = 0; wdx < 8; ++wdx) s += red[wdx][tid*4+cc];
            l[cc] = s + b2[cc];
        }
        float inv_t = expf(-lt[tid]);
#pragma unroll
        for (int cc = 0; cc < 4; ++cc) l[cc] *= inv_t;
        float m = fmaxf(fmaxf(l[0], l[1]), fmaxf(l[2], l[3]));
        float e[4], ssum = 0.f;
#pragma unroll
        for (int cc = 0; cc < 4; ++cc) { e[cc] = expf(l[cc] - m); ssum += e[cc]; }
#pragma unroll
        for (int cc = 0; cc < 4; ++cc) probs[tid][cc] = 0.05f + 0.8f * (e[cc] / ssum);
    }
    __syncthreads();

    float p0 = probs[h][0], p1 = probs[h][1], p2 = probs[h][2], p3 = probs[h][3];
    float4 o;
    o.x = p0*xs0.x + p1*xs1.x + p2*xs2.x + p3*xs3.x;
    o.y = p0*xs0.y + p1*xs1.y + p2*xs2.y + p3*xs3.y;
    o.z = p0*xs0.z + p1*xs1.z + p2*xs2.z + p3*xs3.z;
    o.w = p0*xs0.w + p1*xs1.w + p2*xs2.w + p3*xs3.w;
    float sq = o.x*o.x + o.y*o.y + o.z*o.z + o.w*o.w;
#pragma unroll
    for (int off = 16; off; off >>= 1) sq += __shfl_down_sync(0xffffffff, sq, off);
    __shared__ float psq[8];
    if (lane == 0) psq[wid] = sq;
    __syncthreads();
    float ms = (psq[h*2] + psq[h*2+1]) / 256.f;
    float r = rsqrtf(ms + 1e-5f);
    float4 ow = *(const float4*)&onw[cin];
    float ov[4] = {o.x*r*ow.x, o.y*r*ow.y, o.z*r*ow.z, o.w*r*ow.w};

    int kk = h*256 + cin;
    __nv_bfloat16 hib[4]; float lob[4];
#pragma unroll
    for (int i = 0; i < 4; ++i) {
        hib[i] = __float2bfloat16(ov[i]);
        lob[i] = ov[i] - __bfloat162float(hib[i]);
    }
    *(uint2*)&A2[(size_t)t*2048 + kk] = *(uint2*)hib;
    __nv_bfloat16 lo16[4];
#pragma unroll
    for (int i = 0; i < 4; ++i) lo16[i] = __float2bfloat16(lob[i]);
    *(uint2*)&A2[(size_t)t*2048 + 1024 + kk] = *(uint2*)lo16;
}

// ---------------- launch ----------------------------------------------------------
extern "C" void kernel_launch(void* const* d_in, const int* in_sizes, int n_in,
                              void* d_out, int out_size)
{
    const float* hs = (const float*)d_in[0];
    const float* Wq = (const float*)d_in[1];
    const float* Wk = (const float*)d_in[2];
    const float* Wv = (const float*)d_in[3];
    const float* Wb = (const float*)d_in[4];
    const float* cq = (const float*)d_in[5];
    const float* ck = (const float*)d_in[6];
    const float* cv = (const float*)d_in[7];
    const float* fs = (const float*)d_in[8];
    const float* fl = (const float*)d_in[9];
    const float* w1 = (const float*)d_in[10];
    const float* b1 = (const float*)d_in[11];
    const float* w2 = (const float*)d_in[12];
    const float* b2 = (const float*)d_in[13];
    const float* lt = (const float*)d_in[14];
    const float* onw= (const float*)d_in[15];
    const float* Wo = (const float*)d_in[16];

    const int T = in_sizes[0] / HID;
    const int B = 2;
    const int L = T / B;

    float *tmp3, *q, *k, *v, *kb, *u, *w, *del, *ls, *ll, *g1, *aloc, *beta;
    __nv_bfloat16 *a2, *bth, *btl, *bthg, *btlg, *btho, *btlo;
    cudaGetSymbolAddress((void**)&tmp3, g_tmp3);
    cudaGetSymbolAddress((void**)&q,    g_q);
    cudaGetSymbolAddress((void**)&k,    g_k);
    cudaGetSymbolAddress((void**)&v,    g_v);
    cudaGetSymbolAddress((void**)&kb,   g_kb);
    cudaGetSymbolAddress((void**)&u,    g_u);
    cudaGetSymbolAddress((void**)&w,    g_w);
    cudaGetSymbolAddress((void**)&del,  g_del);
    cudaGetSymbolAddress((void**)&ls,   g_ls);
    cudaGetSymbolAddress((void**)&ll,   g_ll);
    cudaGetSymbolAddress((void**)&g1,   g_g1);
    cudaGetSymbolAddress((void**)&aloc, g_aloc);
    cudaGetSymbolAddress((void**)&beta, g_beta);
    cudaGetSymbolAddress((void**)&a2,   g_a2);
    cudaGetSymbolAddress((void**)&bth,  g_bth);
    cudaGetSymbolAddress((void**)&btl,  g_btl);
    cudaGetSymbolAddress((void**)&bthg, g_bthg);
    cudaGetSymbolAddress((void**)&btlg, g_btlg);
    cudaGetSymbolAddress((void**)&btho, g_btho);
    cudaGetSymbolAddress((void**)&btlo, g_btlo);

    static cudaStream_t s1 = 0, s2 = 0, s3 = 0;
    static cudaEvent_t evS = 0, evA = 0, evQ = 0, evB = 0, evF = 0, evG = 0, evW = 0;
    if (!s1) {
        cudaStreamCreateWithFlags(&s1, cudaStreamNonBlocking);
        cudaStreamCreateWithFlags(&s2, cudaStreamNonBlocking);
        cudaStreamCreateWithFlags(&s3, cudaStreamNonBlocking);
        cudaEventCreateWithFlags(&evS, cudaEventDisableTiming);
        cudaEventCreateWithFlags(&evA, cudaEventDisableTiming);
        cudaEventCreateWithFlags(&evQ, cudaEventDisableTiming);
        cudaEventCreateWithFlags(&evB, cudaEventDisableTiming);
        cudaEventCreateWithFlags(&evF, cudaEventDisableTiming);
        cudaEventCreateWithFlags(&evG, cudaEventDisableTiming);
        cudaEventCreateWithFlags(&evW, cudaEventDisableTiming);
    }

    dim3 bt_grid(HID/32, HID/32);
    dim3 bt_blk(32, 8);
    int nsplit = (T*HID + 255) / 256;

    const int GEMM_SMEM = SST * GSTAGE;
    cudaFuncSetAttribute(gemm_mma, cudaFuncAttributeMaxDynamicSharedMemorySize, GEMM_SMEM);
    size_t chunk_smem = (size_t)(3*32*QP + 32*KTP) * 4;
    size_t scan_smem  = (size_t)(NC*QP + 2*32*QP + 256*KTP + 32*KTP + NC*KTP) * 4;
    cudaFuncSetAttribute(chunk_kernel, cudaFuncAttributeMaxDynamicSharedMemorySize, (int)chunk_smem);
    cudaFuncSetAttribute(scan_kernel,  cudaFuncAttributeMaxDynamicSharedMemorySize, (int)scan_smem);

    // ---- fork point at graph start ----
    cudaEventRecord(evS, 0);

    // ---- s3: beta (needs only hs) ----
    cudaStreamWaitEvent(s3, evS, 0);
    beta_kernel<<<(T*NH + 7) / 8, 256, 0, s3>>>(hs, Wb, beta, T);
    cudaEventRecord(evB, s3);

    // ---- s2: QKV weight splits ----
    cudaStreamWaitEvent(s2, evS, 0);
    bsplit_kernel<<<bt_grid, bt_blk, 0, s2>>>(Wq, bth,             btl,             HID, HID);
    bsplit_kernel<<<bt_grid, bt_blk, 0, s2>>>(Wk, bth + HID*HID,   btl + HID*HID,   HID, HID);
    bsplit_kernel<<<bt_grid, bt_blk, 0, s2>>>(Wv, bth + 2*HID*HID, btl + 2*HID*HID, HID, HID);
    cudaEventRecord(evW, s2);

    // ---- stream0: split hs ----
    asplit_kernel<<<nsplit, 256>>>(hs, a2, HID, T*HID);
    cudaEventRecord(evA, 0);

    // ---- s1: gate GEMM chain + Wo split ----
    cudaStreamWaitEvent(s1, evS, 0);
    bsplit_kernel<<<bt_grid, bt_blk, 0, s1>>>(w1, bthg, btlg, HID, HID);
    cudaStreamWaitEvent(s1, evA, 0);
    {
        dim3 gg(HID/BN, T/BM);
        gemm_mma<<<gg, 256, GEMM_SMEM, s1>>>(a2, bthg, btlg, g1, T, HID, HID);
    }
    bsplit_kernel<<<bt_grid, bt_blk, 0, s1>>>(Wo, btho, btlo, HID, HID);
    cudaEventRecord(evG, s1);

    // ---- stream0: QKV GEMM + fused conv/norm ----
    cudaStreamWaitEvent(0, evW, 0);
    {
        dim3 gg(3*HID/BN, T/BM);
        gemm_mma<<<gg, 256, GEMM_SMEM>>>(a2, bth, btl, tmp3, T, 3*HID, HID);
    }
    cudaStreamWaitEvent(0, evB, 0);
    conv_qkvn_kernel<<<T, 256>>>(tmp3, cq, ck, cv, beta, q, k, kb, v, L);
    cudaEventRecord(evQ, 0);

    // ---- s2: FIR (needs v) ----
    cudaStreamWaitEvent(s2, evQ, 0);
    fir_kernel<<<dim3(HID/64, T/64), 256, 0, s2>>>(v, fs, fl, ls, ll, L);
    cudaEventRecord(evF, s2);

    // ---- stream0: delta path ----
    chunk_kernel<<<B*NH*(L/CHUNK), 256, chunk_smem>>>(q, k, kb, v, beta, u, w, aloc, L);
    scan_kernel<<<dim3(DV/NC, B*NH), 256, scan_smem>>>(q, k, u, w, aloc, del, L);

    // ---- join + fused epilogue ----
    cudaStreamWaitEvent(0, evF, 0);
    cudaStreamWaitEvent(0, evG, 0);
    gsm_kernel<<<T, 256>>>(ls, ll, del, v, g1, w1, b1, w2, b2, lt, onw, a2);
    {
        dim3 gg(HID/BN, T/BM);
        gemm_mma<<<gg, 256, GEMM_SMEM>>>(a2, btho, btlo, (float*)d_out, T, HID, HID);
    }
}

// round 14
// speedup vs baseline: 1.0244x; 1.0146x over previous
#include <cuda_runtime.h>
#include <cuda_bf16.h>
#include <math.h>
#include <stdint.h>

#define HID 1024
#define NH 4
#define DK 256
#define DV 256
#define CHUNK 32
#define TMAX 8192
#define QP 260
#define KTP 36
#define NC 16

// ---------------- scratch ----------------
__device__ float g_tmp3 [TMAX*3*HID];
__device__ float g_q    [TMAX*HID];
__device__ float g_k    [TMAX*HID];
__device__ float g_v    [TMAX*HID];
__device__ float g_kb   [TMAX*HID];
__device__ float g_u    [TMAX*HID];
__device__ float g_w    [TMAX*HID];
__device__ float g_del  [TMAX*HID];
__device__ float g_ls   [TMAX*HID];
__device__ float g_ll   [TMAX*HID];
__device__ float g_g1   [TMAX*HID];
__device__ float g_aloc [TMAX*NH*CHUNK];
__device__ float g_beta [TMAX*NH];
__device__ __nv_bfloat16 g_a2 [TMAX*2*HID];
__device__ __nv_bfloat16 g_bth[3*HID*HID];
__device__ __nv_bfloat16 g_btl[3*HID*HID];
__device__ __nv_bfloat16 g_bthg[HID*HID];
__device__ __nv_bfloat16 g_btlg[HID*HID];
__device__ __nv_bfloat16 g_btho[HID*HID];
__device__ __nv_bfloat16 g_btlo[HID*HID];

__device__ __forceinline__ uint32_t smem_u32(const void* p) {
    uint32_t a;
    asm("{ .reg .u64 t; cvta.to.shared.u64 t, %1; cvt.u32.u64 %0, t; }" : "=r"(a) : "l"(p));
    return a;
}
__device__ __forceinline__ void cp16(uint32_t dst, const void* src) {
    asm volatile("cp.async.cg.shared.global [%0], [%1], 16;" :: "r"(dst), "l"(src));
}

// ---- packed fp32x2 FMA helpers (Blackwell family PTX, sm_100+) ----
__device__ __forceinline__ void ffma2(unsigned long long& d,
                                      unsigned long long a, unsigned long long b) {
    asm("fma.rn.f32x2 %0, %1, %2, %0;" : "+l"(d) : "l"(a), "l"(b));
}
__device__ __forceinline__ unsigned long long pk2(float a, float b) {
    unsigned long long r;
    asm("mov.b64 %0, {%1, %2};" : "=l"(r) : "f"(a), "f"(b));
    return r;
}
__device__ __forceinline__ float hadd2(unsigned long long p) {
    float x, y;
    asm("mov.b64 {%0, %1}, %2;" : "=f"(x), "=f"(y) : "l"(p));
    return x + y;
}

// ---------------- precision-split prep ----------------
__global__ void asplit_kernel(const float* __restrict__ X,
                              __nv_bfloat16* __restrict__ A2, int K, int total) {
    int idx = blockIdx.x * blockDim.x + threadIdx.x;
    if (idx >= total) return;
    int m = idx / K, kk = idx - m * K;
    float v = X[idx];
    __nv_bfloat16 hi = __float2bfloat16(v);
    float r = v - __bfloat162float(hi);
    A2[(size_t)m * 2 * K + kk]     = hi;
    A2[(size_t)m * 2 * K + K + kk] = __float2bfloat16(r);
}

__global__ void bsplit_kernel(const float* __restrict__ W,
                              __nv_bfloat16* __restrict__ Bh,
                              __nv_bfloat16* __restrict__ Bl, int K, int N) {
    __shared__ float t[32][33];
    int bn = blockIdx.x * 32, bk = blockIdx.y * 32;
    int x = threadIdx.x, y = threadIdx.y;
    for (int i = y; i < 32; i += 8) t[i][x] = W[(size_t)(bk + i) * N + bn + x];
    __syncthreads();
    for (int i = y; i < 32; i += 8) {
        float v = t[x][i];
        __nv_bfloat16 hi = __float2bfloat16(v);
        float r = v - __bfloat162float(hi);
        Bh[(size_t)(bn + i) * K + bk + x] = hi;
        Bl[(size_t)(bn + i) * K + bk + x] = __float2bfloat16(r);
    }
}

// ---------------- bf16 mma.sync GEMM (3-term split), BK=64, 3-stage -------------
#define BM 128
#define BN 128
#define BK 64
#define APITCH 72
#define ASTAGE (BM * APITCH * 2)
#define GSTAGE (2 * ASTAGE)
#define SST 3

__global__ __launch_bounds__(256) void gemm_mma(
    const __nv_bfloat16* __restrict__ A2, const __nv_bfloat16* __restrict__ Bh,
    const __nv_bfloat16* __restrict__ Bl, float* __restrict__ C,
    int M, int N, int K)
{
    extern __shared__ __align__(16) char gsm[];
    uint32_t sb = smem_u32(gsm);

    const int tid = threadIdx.x;
    const int wid = tid >> 5, lane = tid & 31;
    const int m0 = blockIdx.y * BM, n0 = blockIdx.x * BN;
    const int wm = (wid >> 2) * 64, wn = (wid & 3) * 32;

    const int KBn = K / BK;
    const int NB = 3 * KBn;
    const size_t sA = (size_t)2 * K;

    auto load_stage = [&](int kb, int buf) {
        int seg = kb / KBn;
        int kk = (kb - seg * KBn) * BK;
        const __nv_bfloat16* Ap = A2 + (seg == 1 ? (size_t)K : 0) + kk;
        const __nv_bfloat16* Bp = ((seg == 2) ? Bl : Bh) + kk;
        uint32_t a_s = sb + (uint32_t)buf * GSTAGE;
        uint32_t b_s = a_s + ASTAGE;
#pragma unroll
        for (int i = 0; i < 4; ++i) {
            int idx = i * 256 + tid;
            int row = idx >> 3, ch = idx & 7;
            cp16(a_s + (uint32_t)(row * APITCH + ch * 8) * 2,
                 Ap + (size_t)(m0 + row) * sA + ch * 8);
            cp16(b_s + (uint32_t)(row * APITCH + ch * 8) * 2,
                 Bp + (size_t)(n0 + row) * K + ch * 8);
        }
    };

    float acc[4][4][4];
#pragma unroll
    for (int mt = 0; mt < 4; ++mt)
#pragma unroll
        for (int nt = 0; nt < 4; ++nt)
#pragma unroll
            for (int e = 0; e < 4; ++e) acc[mt][nt][e] = 0.f;

    load_stage(0, 0);
    asm volatile("cp.async.commit_group;" ::: "memory");
    load_stage(1, 1);
    asm volatile("cp.async.commit_group;" ::: "memory");

    int buf = 0;
    for (int kb = 0; kb < NB; ++kb) {
        asm volatile("cp.async.wait_group 1;" ::: "memory");
        __syncthreads();
        if (kb + 2 < NB) load_stage(kb + 2, (buf + 2) % SST);
        asm volatile("cp.async.commit_group;" ::: "memory");

        uint32_t a_s = sb + (uint32_t)buf * GSTAGE;
        uint32_t b_s = a_s + ASTAGE;
#pragma unroll
        for (int kp = 0; kp < 4; ++kp) {
            uint32_t a[4][4], b[4][2];
            {
                int r_off = lane & 15;
                int c_off = kp * 16 + (lane >> 4) * 8;
#pragma unroll
                for (int mt = 0; mt < 4; ++mt) {
                    uint32_t addr = a_s + (uint32_t)((wm + mt * 16 + r_off) * APITCH + c_off) * 2;
                    asm volatile("ldmatrix.sync.aligned.m8n8.x4.shared.b16 {%0,%1,%2,%3}, [%4];"
                        : "=r"(a[mt][0]), "=r"(a[mt][1]), "=r"(a[mt][2]), "=r"(a[mt][3])
                        : "r"(addr));
                }
            }
            {
                int n_off = (lane & 7) + (lane >> 4) * 8;
                int c_off = kp * 16 + ((lane >> 3) & 1) * 8;
#pragma unroll
                for (int nb = 0; nb < 2; ++nb) {
                    uint32_t r0, r1, r2, r3;
                    uint32_t addr = b_s + (uint32_t)((wn + nb * 16 + n_off) * APITCH + c_off) * 2;
                    asm volatile("ldmatrix.sync.aligned.m8n8.x4.shared.b16 {%0,%1,%2,%3}, [%4];"
                        : "=r"(r0), "=r"(r1), "=r"(r2), "=r"(r3) : "r"(addr));
                    b[nb * 2][0] = r0;     b[nb * 2][1] = r1;
                    b[nb * 2 + 1][0] = r2; b[nb * 2 + 1][1] = r3;
                }
            }
#pragma unroll
            for (int mt = 0; mt < 4; ++mt)
#pragma unroll
                for (int nt = 0; nt < 4; ++nt) {
                    asm volatile(
                        "mma.sync.aligned.m16n8k16.row.col.f32.bf16.bf16.f32 "
                        "{%0,%1,%2,%3}, {%4,%5,%6,%7}, {%8,%9}, {%0,%1,%2,%3};"
                        : "+f"(acc[mt][nt][0]), "+f"(acc[mt][nt][1]),
                          "+f"(acc[mt][nt][2]), "+f"(acc[mt][nt][3])
                        : "r"(a[mt][0]), "r"(a[mt][1]), "r"(a[mt][2]), "r"(a[mt][3]),
                          "r"(b[nt][0]), "r"(b[nt][1]));
                }
        }
        __syncthreads();
        buf = (buf + 1) % SST;
    }

    int g = lane >> 2, tg = lane & 3;
#pragma unroll
    for (int mt = 0; mt < 4; ++mt) {
#pragma unroll
        for (int nt = 0; nt < 4; ++nt) {
            int row = m0 + wm + mt * 16 + g;
            int col = n0 + wn + nt * 8 + tg * 2;
            *(float2*)(C + (size_t)row * N + col) =
                make_float2(acc[mt][nt][0], acc[mt][nt][1]);
            *(float2*)(C + (size_t)(row + 8) * N + col) =
                make_float2(acc[mt][nt][2], acc[mt][nt][3]);
        }
    }
}

// ---------------- fused QKV conv + SiLU + l2norm + kb ---------------------------
__global__ __launch_bounds__(256) void conv_qkvn_kernel(
    const float* __restrict__ x3,
    const float* __restrict__ cq, const float* __restrict__ ck,
    const float* __restrict__ cv, const float* __restrict__ beta,
    float* __restrict__ q, float* __restrict__ k,
    float* __restrict__ kb, float* __restrict__ v, int L)
{
    int t = blockIdx.x;
    int b = t / L, l = t % L;
    int tid = threadIdx.x;
    int lane = tid & 31, wid = tid >> 5;
    int c = tid * 4;

    const float* wp[3] = {cq, ck, cv};
    float4 outv[3];
#pragma unroll
    for (int proj = 0; proj < 3; ++proj) {
        int cOff = proj * 1024 + c;
        float4 xv[4];
#pragma unroll
        for (int kk = 0; kk < 4; ++kk) {
            int ll = l - 3 + kk;
            xv[kk] = (ll >= 0) ? *(const float4*)&x3[((size_t)(b*L + ll))*3072 + cOff]
                               : make_float4(0.f, 0.f, 0.f, 0.f);
        }
        const float* w = wp[proj];
        float4 w0 = *(const float4*)&w[(c+0)*4];
        float4 w1 = *(const float4*)&w[(c+1)*4];
        float4 w2 = *(const float4*)&w[(c+2)*4];
        float4 w3 = *(const float4*)&w[(c+3)*4];
        float4 acc;
        acc.x = xv[0].x*w0.x + xv[1].x*w0.y + xv[2].x*w0.z + xv[3].x*w0.w;
        acc.y = xv[0].y*w1.x + xv[1].y*w1.y + xv[2].y*w1.z + xv[3].y*w1.w;
        acc.z = xv[0].z*w2.x + xv[1].z*w2.y + xv[2].z*w2.z + xv[3].z*w2.w;
        acc.w = xv[0].w*w3.x + xv[1].w*w3.y + xv[2].w*w3.z + xv[3].w*w3.w;
        acc.x = acc.x / (1.f + expf(-acc.x));
        acc.y = acc.y / (1.f + expf(-acc.y));
        acc.z = acc.z / (1.f + expf(-acc.z));
        acc.w = acc.w / (1.f + expf(-acc.w));
        outv[proj] = acc;
    }
    *(float4*)&v[(size_t)t*HID + c] = outv[2];

    float4 qa = outv[0], ka = outv[1];
    float sq = qa.x*qa.x + qa.y*qa.y + qa.z*qa.z + qa.w*qa.w;
    float sk = ka.x*ka.x + ka.y*ka.y + ka.z*ka.z + ka.w*ka.w;
#pragma unroll
    for (int off = 16; off; off >>= 1) {
        sq += __shfl_down_sync(0xffffffff, sq, off);
        sk += __shfl_down_sync(0xffffffff, sk, off);
    }
    __shared__ float pq[8], pk[8];
    if (lane == 0) { pq[wid] = sq; pk[wid] = sk; }
    __syncthreads();
    int h = tid >> 6;
    float sumq = pq[h*2] + pq[h*2+1];
    float sumk = pk[h*2] + pk[h*2+1];
    float rq = rsqrtf(sumq + 1e-6f);
    float rk = rsqrtf(sumk + 1e-6f);
    float bb = beta[t*NH + h];
    float4 qn = make_float4(qa.x*rq, qa.y*rq, qa.z*rq, qa.w*rq);
    float4 kn = make_float4(ka.x*rk, ka.y*rk, ka.z*rk, ka.w*rk);
    float4 kbv = make_float4(kn.x*bb, kn.y*bb, kn.z*bb, kn.w*bb);
    *(float4*)&q [(size_t)t*HID + c] = qn;
    *(float4*)&k [(size_t)t*HID + c] = kn;
    *(float4*)&kb[(size_t)t*HID + c] = kbv;
}

// ---------------- fused FIR conv (short K=5 + long K=64), smem-tiled ------------
__global__ __launch_bounds__(256) void fir_kernel(
    const float* __restrict__ V, const float* __restrict__ fs,
    const float* __restrict__ fl, float* __restrict__ LS,
    float* __restrict__ LL, int L)
{
    __shared__ float xs[127*64];
    int ct = blockIdx.x;
    int tt = blockIdx.y;
    int c0 = ct * 64;
    int t0 = tt * 64;
    int b = t0 / L;
    int l0 = t0 - b * L;
    int tid = threadIdx.x;

    for (int idx = tid; idx < 127*64; idx += 256) {
        int row = idx >> 6, c = idx & 63;
        int l = l0 - 63 + row;
        xs[idx] = (l >= 0) ? V[((size_t)(b*L + l))*HID + c0 + c] : 0.f;
    }

    int c = tid & 63;
    int tg = tid >> 6;
    int cg = c0 + c;
    float wl[64];
#pragma unroll
    for (int kk = 0; kk < 64; ++kk) wl[kk] = fl[cg*64 + kk];
    float ws[5];
#pragma unroll
    for (int kk = 0; kk < 5; ++kk) ws[kk] = fs[cg*5 + kk];
    __syncthreads();

    for (int j = 0; j < 16; ++j) {
        int jj = tg*16 + j;
        float accl = 0.f, accs = 0.f;
#pragma unroll
        for (int kk = 0; kk < 64; ++kk) accl += xs[(jj+kk)*64 + c] * wl[kk];
#pragma unroll
        for (int kk = 0; kk < 5; ++kk) accs += xs[(jj+59+kk)*64 + c] * ws[kk];
        size_t o = ((size_t)(t0 + jj))*HID + cg;
        LL[o] = accl;
        LS[o] = accs;
    }
}

// ---------------- beta ------------------------------------------------------------
__global__ void beta_kernel(const float* __restrict__ hs, const float* __restrict__ Wb,
                            float* __restrict__ beta, int T)
{
    int gw = (blockIdx.x * blockDim.x + threadIdx.x) >> 5;
    int lane = threadIdx.x & 31;
    if (gw >= T * NH) return;
    int t = gw / NH, h = gw % NH;
    float s = 0.f;
    for (int r = lane; r < HID; r += 32) s += hs[(size_t)t*HID + r] * Wb[r*NH + h];
#pragma unroll
    for (int off = 16; off; off >>= 1) s += __shfl_down_sync(0xffffffff, s, off);
    if (lane == 0) beta[t*NH + h] = 1.f / (1.f + expf(-s));
}

// ---------------- per-chunk: attn inversion + u, w, attn_loc (f32x2) ------------
__global__ __launch_bounds__(256) void chunk_kernel(
    const float* __restrict__ Qn, const float* __restrict__ Kn,
    const float* __restrict__ KB, const float* __restrict__ V,
    const float* __restrict__ beta, float* __restrict__ U,
    float* __restrict__ Wbuf, float* __restrict__ Aloc, int L)
{
    extern __shared__ float sm[];
    float* q_s  = sm;
    float* kn_s = q_s  + 32*QP;
    float* kb_s = kn_s + 32*QP;
    float* A    = kb_s + 32*QP;
    int nch = L / CHUNK;
    int cid = blockIdx.x;
    int ch = cid % nch;
    int h  = (cid / nch) & (NH - 1);
    int b  = cid / (nch * NH);
    int l0 = ch * CHUNK;
    int tid = threadIdx.x;
    int lane = tid & 31;
    int iw = tid >> 5;
    size_t base = ((size_t)(b*L + l0)) * HID + h*DK;

#pragma unroll
    for (int it = 0; it < 8; ++it) {
        int idx = it * 256 + tid;
        int row = idx >> 6, cg4 = (idx & 63) * 4;
        size_t g = base + (size_t)row*HID + cg4;
        *(float4*)&q_s [row*QP + cg4] = *(const float4*)&Qn[g];
        *(float4*)&kn_s[row*QP + cg4] = *(const float4*)&Kn[g];
        *(float4*)&kb_s[row*QP + cg4] = *(const float4*)&KB[g];
    }
    __syncthreads();

    size_t abase = (size_t)cid * (CHUNK*CHUNK);
#pragma unroll
    for (int r = 0; r < 4; ++r) {
        int i = r*8 + iw, j = lane;
        unsigned long long sA2 = 0ull, sL2 = 0ull;
#pragma unroll 8
        for (int dq = 0; dq < 64; ++dq) {
            ulonglong2 kn = *(ulonglong2*)&kn_s[j*QP + dq*4];
            ulonglong2 kbv = *(ulonglong2*)&kb_s[i*QP + dq*4];
            ulonglong2 qv = *(ulonglong2*)&q_s [i*QP + dq*4];
            ffma2(sA2, kbv.x, kn.x); ffma2(sA2, kbv.y, kn.y);
            ffma2(sL2, qv.x, kn.x);  ffma2(sL2, qv.y, kn.y);
        }
        float sA = hadd2(sA2), sL = hadd2(sL2);
        A[i*KTP + j] = (i > j) ? -sA : 0.f;
        Aloc[abase + i*32 + j] = (j <= i) ? sL : 0.f;
    }
    __syncthreads();

    if (tid < 32) {
        int j = tid;
        for (int i = 1; i < 32; ++i) {
            float s = 0.f;
            if (j < i) {
#pragma unroll
                for (int t2 = 0; t2 < 32; ++t2) s += A[i*KTP + t2] * A[t2*KTP + j];
            }
            __syncwarp();
            if (j < i) A[i*KTP + j] += s;
            __syncwarp();
        }
        A[j*KTP + j] += 1.f;
    }
    __syncthreads();

#pragma unroll
    for (int it = 0; it < 8; ++it) {
        int idx = it * 256 + tid;
        int row = idx >> 6, cg4 = (idx & 63) * 4;
        float bb = beta[(b*L + l0 + row)*NH + h];
        float4 vv = *(const float4*)&V[base + (size_t)row*HID + cg4];
        *(float4*)&q_s[row*QP + cg4] =
            make_float4(vv.x*bb, vv.y*bb, vv.z*bb, vv.w*bb);
    }
    __syncthreads();

    // hoist columns as packed pairs (t2 pairs)
    unsigned long long vc2[16], kc2[16];
#pragma unroll
    for (int t2 = 0; t2 < 16; ++t2) {
        vc2[t2] = pk2(q_s [(2*t2)*QP + tid], q_s [(2*t2+1)*QP + tid]);
        kc2[t2] = pk2(kb_s[(2*t2)*QP + tid], kb_s[(2*t2+1)*QP + tid]);
    }

    for (int i = 0; i < 32; ++i) {
        unsigned long long su2 = 0ull, sw2 = 0ull;
#pragma unroll
        for (int qq = 0; qq < 8; ++qq) {
            ulonglong2 a = *(ulonglong2*)&A[i*KTP + qq*4];
            ffma2(su2, a.x, vc2[qq*2]);     ffma2(su2, a.y, vc2[qq*2+1]);
            ffma2(sw2, a.x, kc2[qq*2]);     ffma2(sw2, a.y, kc2[qq*2+1]);
        }
        U   [base + (size_t)i*HID + tid] = hadd2(su2);
        Wbuf[base + (size_t)i*HID + tid] = hadd2(sw2);
    }
}

// ---------------- sequential chunk scan (f32x2 packed FMA) ----------------------
__global__ __launch_bounds__(256) void scan_kernel(
    const float* __restrict__ Qn, const float* __restrict__ Kn,
    const float* __restrict__ U,  const float* __restrict__ Wbuf,
    const float* __restrict__ Aloc, float* __restrict__ Dout, int L)
{
    extern __shared__ float sm[];
    float* Ssm_t = sm;
    float* q_s   = Ssm_t + NC*QP;
    float* w_s   = q_s   + 32*QP;
    float* k_t   = w_s   + 32*QP;
    float* al    = k_t   + 256*KTP;
    float* ul_t  = al    + 32*KTP;

    int cb = blockIdx.x;
    int bh = blockIdx.y;
    int b = bh >> 2, h = bh & 3;
    int tid = threadIdx.x;
    int c  = tid & (NC - 1);
    int gi = tid >> 4;
    int nch = L / CHUNK;

    unsigned long long Sreg2[16];            // packed partial sums of S[d][c]
#pragma unroll
    for (int r = 0; r < 16; ++r) Sreg2[r] = 0ull;

    for (int ch = 0; ch < nch; ++ch) {
        int l0 = ch * CHUNK;
        size_t base = ((size_t)(b*L + l0)) * HID + h*DK;

        // S image (scalar = lo+hi of packed partials)
#pragma unroll
        for (int r = 0; r < 16; ++r) Ssm_t[c*QP + r*16 + gi] = hadd2(Sreg2[r]);
#pragma unroll
        for (int it = 0; it < 8; ++it) {
            int idx = it * 256 + tid;
            int row = idx >> 6, cg4 = (idx & 63) * 4;
            size_t g = base + (size_t)row*HID + cg4;
            *(float4*)&q_s[row*QP + cg4] = *(const float4*)&Qn[g];
            *(float4*)&w_s[row*QP + cg4] = *(const float4*)&Wbuf[g];
            float4 kv = *(const float4*)&Kn[g];
            k_t[(cg4+0)*KTP + row] = kv.x;
            k_t[(cg4+1)*KTP + row] = kv.y;
            k_t[(cg4+2)*KTP + row] = kv.z;
            k_t[(cg4+3)*KTP + row] = kv.w;
        }
        size_t abase = (size_t)((b*NH + h)*nch + ch) * 1024;
#pragma unroll
        for (int e0 = 0; e0 < 4; ++e0) {
            int e = e0*256 + tid;
            al[(e >> 5)*KTP + (e & 31)] = Aloc[abase + e];
        }

        float u0[2];
#pragma unroll
        for (int r2 = 0; r2 < 2; ++r2)
            u0[r2] = U[((size_t)(b*L + l0 + (r2*16 + gi)))*HID + h*DV + cb*NC + c];
        __syncthreads();

        // packed: ws2 = w@S partials, os2 = q@S partials
        unsigned long long ws2[2] = {0ull, 0ull}, os2[2] = {0ull, 0ull};
#pragma unroll 4
        for (int dq = 0; dq < 64; ++dq) {
            ulonglong2 sv = *(ulonglong2*)&Ssm_t[c*QP + dq*4];
#pragma unroll
            for (int r2 = 0; r2 < 2; ++r2) {
                int i = r2*16 + gi;
                ulonglong2 wv = *(ulonglong2*)&w_s[i*QP + dq*4];
                ulonglong2 qv = *(ulonglong2*)&q_s[i*QP + dq*4];
                ffma2(ws2[r2], wv.x, sv.x); ffma2(ws2[r2], wv.y, sv.y);
                ffma2(os2[r2], qv.x, sv.x); ffma2(os2[r2], qv.y, sv.y);
            }
        }
#pragma unroll
        for (int r2 = 0; r2 < 2; ++r2)
            ul_t[c*KTP + r2*16 + gi] = u0[r2] - hadd2(ws2[r2]);
        __syncthreads();

        // hoist u_loc column as packed pairs
        unsigned long long ulreg2[16];
#pragma unroll
        for (int qq = 0; qq < 8; ++qq) {
            ulonglong2 t4 = *(ulonglong2*)&ul_t[c*KTP + qq*4];
            ulreg2[qq*2]   = t4.x;
            ulreg2[qq*2+1] = t4.y;
        }

        // o2 = attn_loc @ u_loc (accumulate into os2)
#pragma unroll
        for (int qq = 0; qq < 8; ++qq) {
#pragma unroll
            for (int r2 = 0; r2 < 2; ++r2) {
                int i = r2*16 + gi;
                ulonglong2 av = *(ulonglong2*)&al[i*KTP + qq*4];
                ffma2(os2[r2], av.x, ulreg2[qq*2]);
                ffma2(os2[r2], av.y, ulreg2[qq*2+1]);
            }
        }
#pragma unroll
        for (int r2 = 0; r2 < 2; ++r2)
            Dout[((size_t)(b*L + l0 + (r2*16 + gi)))*HID + h*DV + cb*NC + c] = hadd2(os2[r2]);

        // S += k^T @ u_loc (packed partial accumulation)
#pragma unroll
        for (int qq = 0; qq < 8; ++qq) {
#pragma unroll
            for (int r = 0; r < 16; ++r) {
                ulonglong2 kv = *(ulonglong2*)&k_t[(r*16 + gi)*KTP + qq*4];
                ffma2(Sreg2[r], kv.x, ulreg2[qq*2]);
                ffma2(Sreg2[r], kv.y, ulreg2[qq*2+1]);
            }
        }
        __syncthreads();
    }
}

// ---------------- fused stats + gate MLP + softmax + mix + RMSNorm + split ------
__global__ __launch_bounds__(256) void gsm_kernel(
    const float* __restrict__ LS, const float* __restrict__ LL,
    const float* __restrict__ DEL, const float* __restrict__ V,
    const float* __restrict__ G1,
    const float* __restrict__ w1, const float* __restrict__ b1,
    const float* __restrict__ w2, const float* __restrict__ b2,
    const float* __restrict__ lt, const float* __restrict__ onw,
    __nv_bfloat16* __restrict__ A2)
{
    int t = blockIdx.x;
    int tid = threadIdx.x;
    int lane = tid & 31, wid = tid >> 5;
    int h = tid >> 6;
    int cin = (tid & 63) * 4;

    size_t base = (size_t)t*1024 + h*256 + cin;
    float4 xs0 = *(const float4*)&LS [base];
    float4 xs1 = *(const float4*)&LL [base];
    float4 xs2 = *(const float4*)&DEL[base];
    float4 xs3 = *(const float4*)&V  [base];

    __shared__ float wstat[8][12];
    {
        float4 xs[4] = {xs0, xs1, xs2, xs3};
#pragma unroll
        for (int sig = 0; sig < 4; ++sig) {
            float4 x = xs[sig];
            float s1 = x.x + x.y + x.z + x.w;
            float s2 = x.x*x.x + x.y*x.y + x.z*x.z + x.w*x.w;
            float s3 = fabsf(x.x) + fabsf(x.y) + fabsf(x.z) + fabsf(x.w);
#pragma unroll
            for (int off = 16; off; off >>= 1) {
                s1 += __shfl_down_sync(0xffffffff, s1, off);
                s2 += __shfl_down_sync(0xffffffff, s2, off);
                s3 += __shfl_down_sync(0xffffffff, s3, off);
            }
            if (lane == 0) {
                wstat[wid][sig*3+0] = s1;
                wstat[wid][sig*3+1] = s2;
                wstat[wid][sig*3+2] = s3;
            }
        }
    }
    __syncthreads();

    __shared__ float st[4][16];
    if (tid < 64) {
        int hh = tid >> 4, idx = tid & 15, sig = idx >> 2, which = idx & 3;
        float s1 = wstat[hh*2][sig*3+0] + wstat[hh*2+1][sig*3+0];
        float s2 = wstat[hh*2][sig*3+1] + wstat[hh*2+1][sig*3+1];
        float s3 = wstat[hh*2][sig*3+2] + wstat[hh*2+1][sig*3+2];
        float mean = s1 / 256.f;
        float val;
        if (which == 0)      val = mean;
        else if (which == 1) val = s2 / 256.f - mean*mean;
        else if (which == 2) val = s3 / 256.f;
        else                 val = sqrtf(s2);
        st[hh][idx] = val;
    }
    __syncthreads();

    float p[4][4];
#pragma unroll
    for (int hh = 0; hh < 4; ++hh)
#pragma unroll
        for (int cc = 0; cc < 4; ++cc) p[hh][cc] = 0.f;

#pragma unroll
    for (int jj = 0; jj < 4; ++jj) {
        int j = jj*256 + tid;
        float xb = G1[(size_t)t*1024 + j] + b1[j];
        float w1v[16];
#pragma unroll
        for (int s = 0; s < 16; ++s) w1v[s] = w1[(size_t)(1024 + s)*1024 + j];
        float4 w2v = *(const float4*)&w2[j*4];
#pragma unroll
        for (int hh = 0; hh < 4; ++hh) {
            float x = xb;
#pragma unroll
            for (int s = 0; s < 16; ++s) x += st[hh][s] * w1v[s];
            float g = 0.5f * x * (1.f + erff(x * 0.70710678118654752f));
            p[hh][0] += g * w2v.x; p[hh][1] += g * w2v.y;
            p[hh][2] += g * w2v.z; p[hh][3] += g * w2v.w;
        }
    }
#pragma unroll
    for (int hh = 0; hh < 4; ++hh)
#pragma unroll
        for (int cc = 0; cc < 4; ++cc) {
            float vsum = p[hh][cc];
#pragma unroll
            for (int off = 16; off; off >>= 1)
                vsum += __shfl_down_sync(0xffffffff, vsum, off);
            p[hh][cc] = vsum;
        }
    __shared__ float red[8][16];
    if (lane == 0) {
#pragma unroll
        for (int hh = 0; hh < 4; ++hh)
#pragma unroll
            for (int cc = 0; cc < 4; ++cc) red[wid][hh*4+cc] = p[hh][cc];
    }
    __syncthreads();

    __shared__ float probs[4][4];
    if (tid < 4) {
        float l[4];
#pragma unroll
        for (int cc = 0; cc < 4; ++cc) {
            float s = 0.f;
#pragma unroll
            for (int wdx = 0; wdx < 8; ++wdx) s += red[wdx][tid*4+cc];
            l[cc] = s + b2[cc];
        }
        float inv_t = expf(-lt[tid]);
#pragma unroll
        for (int cc = 0; cc < 4; ++cc) l[cc] *= inv_t;
        float m = fmaxf(fmaxf(l[0], l[1]), fmaxf(l[2], l[3]));
        float e[4], ssum = 0.f;
#pragma unroll
        for (int cc = 0; cc < 4; ++cc) { e[cc] = expf(l[cc] - m); ssum += e[cc]; }
#pragma unroll
        for (int cc = 0; cc < 4; ++cc) probs[tid][cc] = 0.05f + 0.8f * (e[cc] / ssum);
    }
    __syncthreads();

    float p0 = probs[h][0], p1 = probs[h][1], p2 = probs[h][2], p3 = probs[h][3];
    float4 o;
    o.x = p0*xs0.x + p1*xs1.x + p2*xs2.x + p3*xs3.x;
    o.y = p0*xs0.y + p1*xs1.y + p2*xs2.y + p3*xs3.y;
    o.z = p0*xs0.z + p1*xs1.z + p2*xs2.z + p3*xs3.z;
    o.w = p0*xs0.w + p1*xs1.w + p2*xs2.w + p3*xs3.w;
    float sq = o.x*o.x + o.y*o.y + o.z*o.z + o.w*o.w;
#pragma unroll
    for (int off = 16; off; off >>= 1) sq += __shfl_down_sync(0xffffffff, sq, off);
    __shared__ float psq[8];
    if (lane == 0) psq[wid] = sq;
    __syncthreads();
    float ms = (psq[h*2] + psq[h*2+1]) / 256.f;
    float r = rsqrtf(ms + 1e-5f);
    float4 ow = *(const float4*)&onw[cin];
    float ov[4] = {o.x*r*ow.x, o.y*r*ow.y, o.z*r*ow.z, o.w*r*ow.w};

    int kk = h*256 + cin;
    __nv_bfloat16 hib[4]; float lob[4];
#pragma unroll
    for (int i = 0; i < 4; ++i) {
        hib[i] = __float2bfloat16(ov[i]);
        lob[i] = ov[i] - __bfloat162float(hib[i]);
    }
    *(uint2*)&A2[(size_t)t*2048 + kk] = *(uint2*)hib;
    __nv_bfloat16 lo16[4];
#pragma unroll
    for (int i = 0; i < 4; ++i) lo16[i] = __float2bfloat16(lob[i]);
    *(uint2*)&A2[(size_t)t*2048 + 1024 + kk] = *(uint2*)lo16;
}

// ---------------- launch ----------------------------------------------------------
extern "C" void kernel_launch(void* const* d_in, const int* in_sizes, int n_in,
                              void* d_out, int out_size)
{
    const float* hs = (const float*)d_in[0];
    const float* Wq = (const float*)d_in[1];
    const float* Wk = (const float*)d_in[2];
    const float* Wv = (const float*)d_in[3];
    const float* Wb = (const float*)d_in[4];
    const float* cq = (const float*)d_in[5];
    const float* ck = (const float*)d_in[6];
    const float* cv = (const float*)d_in[7];
    const float* fs = (const float*)d_in[8];
    const float* fl = (const float*)d_in[9];
    const float* w1 = (const float*)d_in[10];
    const float* b1 = (const float*)d_in[11];
    const float* w2 = (const float*)d_in[12];
    const float* b2 = (const float*)d_in[13];
    const float* lt = (const float*)d_in[14];
    const float* onw= (const float*)d_in[15];
    const float* Wo = (const float*)d_in[16];

    const int T = in_sizes[0] / HID;
    const int B = 2;
    const int L = T / B;

    float *tmp3, *q, *k, *v, *kb, *u, *w, *del, *ls, *ll, *g1, *aloc, *beta;
    __nv_bfloat16 *a2, *bth, *btl, *bthg, *btlg, *btho, *btlo;
    cudaGetSymbolAddress((void**)&tmp3, g_tmp3);
    cudaGetSymbolAddress((void**)&q,    g_q);
    cudaGetSymbolAddress((void**)&k,    g_k);
    cudaGetSymbolAddress((void**)&v,    g_v);
    cudaGetSymbolAddress((void**)&kb,   g_kb);
    cudaGetSymbolAddress((void**)&u,    g_u);
    cudaGetSymbolAddress((void**)&w,    g_w);
    cudaGetSymbolAddress((void**)&del,  g_del);
    cudaGetSymbolAddress((void**)&ls,   g_ls);
    cudaGetSymbolAddress((void**)&ll,   g_ll);
    cudaGetSymbolAddress((void**)&g1,   g_g1);
    cudaGetSymbolAddress((void**)&aloc, g_aloc);
    cudaGetSymbolAddress((void**)&beta, g_beta);
    cudaGetSymbolAddress((void**)&a2,   g_a2);
    cudaGetSymbolAddress((void**)&bth,  g_bth);
    cudaGetSymbolAddress((void**)&btl,  g_btl);
    cudaGetSymbolAddress((void**)&bthg, g_bthg);
    cudaGetSymbolAddress((void**)&btlg, g_btlg);
    cudaGetSymbolAddress((void**)&btho, g_btho);
    cudaGetSymbolAddress((void**)&btlo, g_btlo);

    static cudaStream_t s1 = 0, s2 = 0, s3 = 0;
    static cudaEvent_t evS = 0, evA = 0, evQ = 0, evB = 0, evF = 0, evG = 0, evW = 0;
    if (!s1) {
        cudaStreamCreateWithFlags(&s1, cudaStreamNonBlocking);
        cudaStreamCreateWithFlags(&s2, cudaStreamNonBlocking);
        cudaStreamCreateWithFlags(&s3, cudaStreamNonBlocking);
        cudaEventCreateWithFlags(&evS, cudaEventDisableTiming);
        cudaEventCreateWithFlags(&evA, cudaEventDisableTiming);
        cudaEventCreateWithFlags(&evQ, cudaEventDisableTiming);
        cudaEventCreateWithFlags(&evB, cudaEventDisableTiming);
        cudaEventCreateWithFlags(&evF, cudaEventDisableTiming);
        cudaEventCreateWithFlags(&evG, cudaEventDisableTiming);
        cudaEventCreateWithFlags(&evW, cudaEventDisableTiming);
    }

    dim3 bt_grid(HID/32, HID/32);
    dim3 bt_blk(32, 8);
    int nsplit = (T*HID + 255) / 256;

    const int GEMM_SMEM = SST * GSTAGE;
    cudaFuncSetAttribute(gemm_mma, cudaFuncAttributeMaxDynamicSharedMemorySize, GEMM_SMEM);
    size_t chunk_smem = (size_t)(3*32*QP + 32*KTP) * 4;
    size_t scan_smem  = (size_t)(NC*QP + 2*32*QP + 256*KTP + 32*KTP + NC*KTP) * 4;
    cudaFuncSetAttribute(chunk_kernel, cudaFuncAttributeMaxDynamicSharedMemorySize, (int)chunk_smem);
    cudaFuncSetAttribute(scan_kernel,  cudaFuncAttributeMaxDynamicSharedMemorySize, (int)scan_smem);

    // ---- fork point at graph start ----
    cudaEventRecord(evS, 0);

    // ---- s3: beta ----
    cudaStreamWaitEvent(s3, evS, 0);
    beta_kernel<<<(T*NH + 7) / 8, 256, 0, s3>>>(hs, Wb, beta, T);
    cudaEventRecord(evB, s3);

    // ---- s2: QKV weight splits ----
    cudaStreamWaitEvent(s2, evS, 0);
    bsplit_kernel<<<bt_grid, bt_blk, 0, s2>>>(Wq, bth,             btl,             HID, HID);
    bsplit_kernel<<<bt_grid, bt_blk, 0, s2>>>(Wk, bth + HID*HID,   btl + HID*HID,   HID, HID);
    bsplit_kernel<<<bt_grid, bt_blk, 0, s2>>>(Wv, bth + 2*HID*HID, btl + 2*HID*HID, HID, HID);
    cudaEventRecord(evW, s2);

    // ---- stream0: split hs ----
    asplit_kernel<<<nsplit, 256>>>(hs, a2, HID, T*HID);
    cudaEventRecord(evA, 0);

    // ---- s1: gate GEMM chain + Wo split ----
    cudaStreamWaitEvent(s1, evS, 0);
    bsplit_kernel<<<bt_grid, bt_blk, 0, s1>>>(w1, bthg, btlg, HID, HID);
    cudaStreamWaitEvent(s1, evA, 0);
    {
        dim3 gg(HID/BN, T/BM);
        gemm_mma<<<gg, 256, GEMM_SMEM, s1>>>(a2, bthg, btlg, g1, T, HID, HID);
    }
    bsplit_kernel<<<bt_grid, bt_blk, 0, s1>>>(Wo, btho, btlo, HID, HID);
    cudaEventRecord(evG, s1);

    // ---- stream0: QKV GEMM + fused conv/norm ----
    cudaStreamWaitEvent(0, evW, 0);
    {
        dim3 gg(3*HID/BN, T/BM);
        gemm_mma<<<gg, 256, GEMM_SMEM>>>(a2, bth, btl, tmp3, T, 3*HID, HID);
    }
    cudaStreamWaitEvent(0, evB, 0);
    conv_qkvn_kernel<<<T, 256>>>(tmp3, cq, ck, cv, beta, q, k, kb, v, L);
    cudaEventRecord(evQ, 0);

    // ---- s2: FIR (needs v) ----
    cudaStreamWaitEvent(s2, evQ, 0);
    fir_kernel<<<dim3(HID/64, T/64), 256, 0, s2>>>(v, fs, fl, ls, ll, L);
    cudaEventRecord(evF, s2);

    // ---- stream0: delta path ----
    chunk_kernel<<<B*NH*(L/CHUNK), 256, chunk_smem>>>(q, k, kb, v, beta, u, w, aloc, L);
    scan_kernel<<<dim3(DV/NC, B*NH), 256, scan_smem>>>(q, k, u, w, aloc, del, L);

    // ---- join + fused epilogue ----
    cudaStreamWaitEvent(0, evF, 0);
    cudaStreamWaitEvent(0, evG, 0);
    gsm_kernel<<<T, 256>>>(ls, ll, del, v, g1, w1, b1, w2, b2, lt, onw, a2);
    {
        dim3 gg(HID/BN, T/BM);
        gemm_mma<<<gg, 256, GEMM_SMEM>>>(a2, btho, btlo, (float*)d_out, T, HID, HID);
    }
}